// round 9
// baseline (speedup 1.0000x reference)
#include <cuda_runtime.h>
#include <cuda_bf16.h>
#include <cstdint>

#define Bdim 64
#define Kdim 16
#define NN   256
#define QT   128

// ---------------- pre-converted operand scratch (device globals) ----------------
__device__ __nv_bfloat16 g_qh[Bdim*NN*NN];   // [b][q][d] hi
__device__ __nv_bfloat16 g_ql[Bdim*NN*NN];
__device__ __nv_bfloat16 g_dh[Bdim*NN*NN];   // [b][d][a]  (DA transposed)
__device__ __nv_bfloat16 g_dl[Bdim*NN*NN];
__device__ __nv_bfloat16 g_wh[Kdim*NN*NN];   // [k][d][e]
__device__ __nv_bfloat16 g_wl[Kdim*NN*NN];
__device__ float g_vq[Bdim*Kdim*NN];
__device__ float g_vd[Bdim*Kdim*NN];

// ---------------- helpers ----------------
__device__ __forceinline__ void cvt2(float x, __nv_bfloat16& h, __nv_bfloat16& l) {
    h = __float2bfloat16(x);
    l = __float2bfloat16(x - __bfloat162float(h));
}
__device__ __forceinline__ uint32_t pack2(__nv_bfloat16 a, __nv_bfloat16 b) {
    __nv_bfloat162 v(a, b);
    return *(uint32_t*)&v;
}
__device__ __forceinline__ float sigf(float x) { return 1.0f / (1.0f + __expf(-x)); }

// ---------------- prep kernels ----------------
__global__ void cvt_q_kernel(const float4* __restrict__ q4) {
    int i = blockIdx.x * 256 + threadIdx.x;   // 4096 blocks
    float4 v = q4[i];
    __nv_bfloat16 h0,h1,h2,h3,l0,l1,l2,l3;
    cvt2(v.x,h0,l0); cvt2(v.y,h1,l1); cvt2(v.z,h2,l2); cvt2(v.w,h3,l3);
    ((uint2*)g_qh)[i] = make_uint2(pack2(h0,h1), pack2(h2,h3));
    ((uint2*)g_ql)[i] = make_uint2(pack2(l0,l1), pack2(l2,l3));
}
__global__ void cvt_w_kernel(const float4* __restrict__ w4) {
    int i = blockIdx.x * 256 + threadIdx.x;   // 1024 blocks
    float4 v = w4[i];
    __nv_bfloat16 h0,h1,h2,h3,l0,l1,l2,l3;
    cvt2(v.x,h0,l0); cvt2(v.y,h1,l1); cvt2(v.z,h2,l2); cvt2(v.w,h3,l3);
    ((uint2*)g_wh)[i] = make_uint2(pack2(h0,h1), pack2(h2,h3));
    ((uint2*)g_wl)[i] = make_uint2(pack2(l0,l1), pack2(l2,l3));
}
// DA: [b][a][d] fp32 -> [b][d][a] bf16 hi/lo
__global__ void cvt_daT_kernel(const float* __restrict__ da) {
    __shared__ float tile[32][33];
    int b = blockIdx.z, a0 = blockIdx.x * 32, d0 = blockIdx.y * 32;
    int tx = threadIdx.x, ty = threadIdx.y;   // 32 x 8
    const float* src = da + ((size_t)b * NN + a0) * NN + d0;
    #pragma unroll
    for (int i = 0; i < 4; i++)
        tile[ty + 8*i][tx] = src[(size_t)(ty + 8*i) * NN + tx];
    __syncthreads();
    #pragma unroll
    for (int i = 0; i < 4; i++) {
        int dl = ty + 8*i;
        float v = tile[tx][dl];
        __nv_bfloat16 h, l; cvt2(v, h, l);
        size_t o = ((size_t)b * NN + d0 + dl) * NN + a0 + tx;
        g_dh[o] = h; g_dl[o] = l;
    }
}
__global__ void vqvd_kernel(const float* __restrict__ q_em, const float* __restrict__ da_em,
                            const float* __restrict__ V) {
    __shared__ float Vs[16 * NN];
    int bx = blockIdx.x;            // 256 blocks
    int b = bx >> 2, which = (bx >> 1) & 1, h = bx & 1;
    int t = threadIdx.x;            // 128 threads
    #pragma unroll
    for (int i = 0; i < 32; i++) {
        int idx = i * 128 + t, k = idx >> 8, d = idx & 255;
        Vs[idx] = V[k * 512 + which * 256 + d];
    }
    __syncthreads();
    int row = h * 128 + t;
    const float* src = (which ? da_em : q_em) + (size_t)(b * NN + row) * NN;
    float* dst = (which ? g_vd : g_vq);
    float acc[16];
    #pragma unroll
    for (int k = 0; k < 16; k++) acc[k] = 0.f;
    const float4* r4 = (const float4*)src;
    const float4* Vs4 = (const float4*)Vs;
    for (int d4 = 0; d4 < 64; d4++) {
        float4 x = r4[d4];
        #pragma unroll
        for (int k = 0; k < 16; k++) {
            float4 v = Vs4[k * 64 + d4];
            acc[k] += x.x*v.x + x.y*v.y + x.z*v.z + x.w*v.w;
        }
    }
    #pragma unroll
    for (int k = 0; k < 16; k++) dst[(b * 16 + k) * NN + row] = acc[k];
}

// ---------------- mma/ldsm wrappers ----------------
__device__ __forceinline__ void ldsm_x4(unsigned* r, uint32_t addr) {
    asm volatile("ldmatrix.sync.aligned.m8n8.x4.shared.b16 {%0,%1,%2,%3}, [%4];"
                 : "=r"(r[0]), "=r"(r[1]), "=r"(r[2]), "=r"(r[3]) : "r"(addr));
}
__device__ __forceinline__ void ldsm_x4t(unsigned* r, uint32_t addr) {
    asm volatile("ldmatrix.sync.aligned.m8n8.x4.trans.shared.b16 {%0,%1,%2,%3}, [%4];"
                 : "=r"(r[0]), "=r"(r[1]), "=r"(r[2]), "=r"(r[3]) : "r"(addr));
}
__device__ __forceinline__ void mma_bf16(float* c, const unsigned* a, unsigned b0, unsigned b1) {
    asm volatile("mma.sync.aligned.m16n8k16.row.col.f32.bf16.bf16.f32 "
                 "{%0,%1,%2,%3}, {%4,%5,%6,%7}, {%8,%9}, {%0,%1,%2,%3};"
                 : "+f"(c[0]), "+f"(c[1]), "+f"(c[2]), "+f"(c[3])
                 : "r"(a[0]), "r"(a[1]), "r"(a[2]), "r"(a[3]), "r"(b0), "r"(b1));
}
__device__ __forceinline__ void cpa16(uint32_t dst, const void* src) {
    asm volatile("cp.async.cg.shared.global [%0], [%1], 16;" :: "r"(dst), "l"(src) : "memory");
}
#define CP_COMMIT() asm volatile("cp.async.commit_group;" ::: "memory")
#define CP_WAIT(n)  asm volatile("cp.async.wait_group %0;" :: "n"(n) : "memory")

// ---------------- SMEM layout (bytes) ----------------
#define TS_H 0
#define TS_L 65536
#define S1_OFF 131072
#define S1_STRIDE 29184
#define QS_H 0
#define QS_L 6144
#define WS_H 12288
#define WS_L 20736
#define S2_OFF 131072              // alias of S1 region
#define S2_STRIDE 16896
#define DA_H 0
#define DA_L 8448
#define VQ_OFF (S1_OFF + 2*S1_STRIDE)   // 189440
#define VD_OFF (VQ_OFF + 512)
#define SMEM_TOTAL (VD_OFF + 1024)      // 190976

#define QP 24    // Q slab pitch (halves)
#define WP 264   // W / DA slab pitch (halves)

// Ts swizzled address: row r (0..127), 16B-unit u (0..31)
__device__ __forceinline__ uint32_t ts_addr(uint32_t base, int r, int u) {
    return base + (uint32_t)(r * 512) + (uint32_t)(((u ^ (r & 7)) << 4));
}

// ---------------- cp.async slab issuers ----------------
__device__ __forceinline__ void s1_issue(uint32_t buf,
    const __nv_bfloat16* qh, const __nv_bfloat16* ql,
    const __nv_bfloat16* wh, const __nv_bfloat16* wl, int d0, int t)
{
    // Q slab: 128 rows x 16 halves, hi+lo -> 512 tasks
    #pragma unroll
    for (int i = 0; i < 2; i++) {
        int task = i * 256 + t;
        int arr = task >> 8, idx = task & 255, row = idx >> 1, ch = idx & 1;
        uint32_t dst = buf + (arr ? QS_L : QS_H) + (uint32_t)(row * QP + ch * 8) * 2;
        const __nv_bfloat16* src = (arr ? ql : qh) + (size_t)row * NN + d0 + ch * 8;
        cpa16(dst, src);
    }
    // W slab: 16 rows x 256 halves, hi+lo -> 1024 tasks
    #pragma unroll
    for (int i = 0; i < 4; i++) {
        int task = i * 256 + t;
        int arr = task >> 9, idx = task & 511, row = idx >> 5, ch = idx & 31;
        uint32_t dst = buf + (arr ? WS_L : WS_H) + (uint32_t)(row * WP + ch * 8) * 2;
        const __nv_bfloat16* src = (arr ? wl : wh) + (size_t)(d0 + row) * NN + ch * 8;
        cpa16(dst, src);
    }
    CP_COMMIT();
}
__device__ __forceinline__ void s2_issue(uint32_t buf,
    const __nv_bfloat16* dth, const __nv_bfloat16* dtl, int e0, int t)
{
    // DA^T slab: 16 rows (d) x 256 halves (a), hi+lo -> 1024 tasks
    #pragma unroll
    for (int i = 0; i < 4; i++) {
        int task = i * 256 + t;
        int arr = task >> 9, idx = task & 511, row = idx >> 5, ch = idx & 31;
        uint32_t dst = buf + (arr ? DA_L : DA_H) + (uint32_t)(row * WP + ch * 8) * 2;
        const __nv_bfloat16* src = (arr ? dtl : dth) + (size_t)(e0 + row) * NN + ch * 8;
        cpa16(dst, src);
    }
    CP_COMMIT();
}

// ---------------- main kernel ----------------
__global__ void __launch_bounds__(256)
ntn_mma_kernel(const float* __restrict__ bias, float* __restrict__ out)
{
    extern __shared__ char sm[];
    const uint32_t smb = (uint32_t)__cvta_generic_to_shared(sm);
    float* vq = (float*)(sm + VQ_OFF);
    float* vd = (float*)(sm + VD_OFF);

    const int t  = threadIdx.x;
    const int bx = blockIdx.x;
    const int qhf = bx & 1;
    const int k   = (bx >> 1) & 15;
    const int b   = bx >> 5;
    const int q0  = qhf * QT;
    const int bk  = b * 16 + k;

    const int warp = t >> 5;
    const int lane = t & 31;
    const int wq   = warp >> 2;   // 0..1: 64 q-rows each
    const int we   = warp & 3;    // 0..3: 64 cols each
    const int grp  = lane >> 2;
    const int tig  = lane & 3;

    // vq/vd from precomputed globals
    if (t < QT) vq[t] = g_vq[bk * NN + q0 + t];
    vd[t] = g_vd[bk * NN + t];

    const __nv_bfloat16* qh_p = g_qh + ((size_t)b * NN + q0) * NN;
    const __nv_bfloat16* ql_p = g_ql + ((size_t)b * NN + q0) * NN;
    const __nv_bfloat16* wh_p = g_wh + (size_t)k * NN * NN;
    const __nv_bfloat16* wl_p = g_wl + (size_t)k * NN * NN;
    const __nv_bfloat16* dh_p = g_dh + (size_t)b * NN * NN;
    const __nv_bfloat16* dl_p = g_dl + (size_t)b * NN * NN;

    // acc[mi][j][c]: mi = m16 tile (4), j = n8 frag (8), c = 4
    float acc[4][8][4];
    #pragma unroll
    for (int mi = 0; mi < 4; mi++)
        #pragma unroll
        for (int j = 0; j < 8; j++)
            #pragma unroll
            for (int c = 0; c < 4; c++) acc[mi][j][c] = 0.f;

    // ldmatrix address components
    const int a_lrow = (lane & 15);
    const int a_cu   = lane >> 4;            // k-half selector
    const int bw_row = lane & 15;            // B (trans): d row

    // =============== Stage 1: T[128][256] = Q @ W_k ===============
    s1_issue(smb + S1_OFF, qh_p, ql_p, wh_p, wl_p, 0, t);

    #pragma unroll 1
    for (int it = 0; it < 16; it++) {
        CP_WAIT(0);                    // slab it resident
        __syncthreads();               // compute(it-1) done everywhere
        if (it + 1 < 16)
            s1_issue(smb + S1_OFF + ((it + 1) & 1) * S1_STRIDE,
                     qh_p, ql_p, wh_p, wl_p, (it + 1) * 16, t);
        uint32_t cur = smb + S1_OFF + (it & 1) * S1_STRIDE;

        unsigned ah[4][4], al[4][4];
        #pragma unroll
        for (int mi = 0; mi < 4; mi++) {
            int arow = wq * 64 + mi * 16 + a_lrow;
            ldsm_x4(ah[mi], cur + QS_H + (uint32_t)(arow * QP + a_cu * 8) * 2);
            ldsm_x4(al[mi], cur + QS_L + (uint32_t)(arow * QP + a_cu * 8) * 2);
        }

        #pragma unroll
        for (int n2 = 0; n2 < 4; n2++) {
            uint32_t eoff = (uint32_t)(bw_row * WP + we * 64 + n2 * 16 + a_cu * 8) * 2;
            unsigned bh[4], bl[4];
            ldsm_x4t(bh, cur + WS_H + eoff);
            ldsm_x4t(bl, cur + WS_L + eoff);
            #pragma unroll
            for (int mi = 0; mi < 4; mi++) {
                float* c0 = acc[mi][2 * n2];
                float* c1 = acc[mi][2 * n2 + 1];
                mma_bf16(c0, ah[mi], bh[0], bh[1]);
                mma_bf16(c0, ah[mi], bl[0], bl[1]);
                mma_bf16(c0, al[mi], bh[0], bh[1]);
                mma_bf16(c1, ah[mi], bh[2], bh[3]);
                mma_bf16(c1, ah[mi], bl[2], bl[3]);
                mma_bf16(c1, al[mi], bh[2], bh[3]);
            }
        }
    }

    // first DA slab into S2 buf0 (disjoint from S1 buf1 still being read by compute(15))
    s2_issue(smb + S2_OFF, dh_p, dl_p, 0, t);

    // -------- write T to swizzled SMEM as bf16 hi/lo --------
    #pragma unroll
    for (int mi = 0; mi < 4; mi++) {
        int r0 = wq * 64 + mi * 16 + grp;
        #pragma unroll
        for (int j = 0; j < 8; j++) {
            int u = we * 8 + j;            // 16B unit of col
            __nv_bfloat16 h0, l0, h1, l1, h2, l2, h3, l3;
            cvt2(acc[mi][j][0], h0, l0); cvt2(acc[mi][j][1], h1, l1);
            cvt2(acc[mi][j][2], h2, l2); cvt2(acc[mi][j][3], h3, l3);
            uint32_t a0 = ts_addr(smb + TS_H, r0, u) + tig * 4;
            uint32_t a1 = ts_addr(smb + TS_H, r0 + 8, u) + tig * 4;
            uint32_t b0 = ts_addr(smb + TS_L, r0, u) + tig * 4;
            uint32_t b1 = ts_addr(smb + TS_L, r0 + 8, u) + tig * 4;
            uint32_t v;
            v = pack2(h0, h1); asm volatile("st.shared.b32 [%0], %1;" :: "r"(a0), "r"(v) : "memory");
            v = pack2(h2, h3); asm volatile("st.shared.b32 [%0], %1;" :: "r"(a1), "r"(v) : "memory");
            v = pack2(l0, l1); asm volatile("st.shared.b32 [%0], %1;" :: "r"(b0), "r"(v) : "memory");
            v = pack2(l2, l3); asm volatile("st.shared.b32 [%0], %1;" :: "r"(b1), "r"(v) : "memory");
        }
    }

    // =============== Stage 2: OUT = T @ DA^T ===============
    #pragma unroll
    for (int mi = 0; mi < 4; mi++)
        #pragma unroll
        for (int j = 0; j < 8; j++)
            #pragma unroll
            for (int c = 0; c < 4; c++) acc[mi][j][c] = 0.f;

    #pragma unroll 1
    for (int it = 0; it < 16; it++) {
        CP_WAIT(0);
        __syncthreads();               // iter0: orders Ts writes + compute(15) before slab1 issue
        if (it + 1 < 16)
            s2_issue(smb + S2_OFF + ((it + 1) & 1) * S2_STRIDE, dh_p, dl_p, (it + 1) * 16, t);
        uint32_t cur = smb + S2_OFF + (it & 1) * S2_STRIDE;

        // A frags from swizzled Ts: unit = it*2 + a_cu
        unsigned ah[4][4], al[4][4];
        int u = it * 2 + a_cu;
        #pragma unroll
        for (int mi = 0; mi < 4; mi++) {
            int arow = wq * 64 + mi * 16 + a_lrow;
            ldsm_x4(ah[mi], ts_addr(smb + TS_H, arow, u));
            ldsm_x4(al[mi], ts_addr(smb + TS_L, arow, u));
        }

        #pragma unroll
        for (int n2 = 0; n2 < 4; n2++) {
            uint32_t aoff = (uint32_t)(bw_row * WP + we * 64 + n2 * 16 + a_cu * 8) * 2;
            unsigned bh[4], bl[4];
            ldsm_x4t(bh, cur + DA_H + aoff);
            ldsm_x4t(bl, cur + DA_L + aoff);
            #pragma unroll
            for (int mi = 0; mi < 4; mi++) {
                float* c0 = acc[mi][2 * n2];
                float* c1 = acc[mi][2 * n2 + 1];
                mma_bf16(c0, ah[mi], bh[0], bh[1]);
                mma_bf16(c0, ah[mi], bl[0], bl[1]);
                mma_bf16(c0, al[mi], bh[0], bh[1]);
                mma_bf16(c1, ah[mi], bh[2], bh[3]);
                mma_bf16(c1, ah[mi], bl[2], bl[3]);
                mma_bf16(c1, al[mi], bh[2], bh[3]);
            }
        }
    }

    // =============== Epilogue: + vq + vd + bias, sigmoid ===============
    const float bkf = bias[k];
    float* ob = out + (((size_t)b * Kdim + k) * NN + q0) * (size_t)NN;
    #pragma unroll
    for (int mi = 0; mi < 4; mi++) {
        int r0 = wq * 64 + mi * 16 + grp;
        float vq0 = vq[r0], vq1 = vq[r0 + 8];
        #pragma unroll
        for (int j = 0; j < 8; j++) {
            int col = we * 64 + j * 8 + tig * 2;
            float vd0 = vd[col], vd1 = vd[col + 1];
            float2 o0, o1;
            o0.x = sigf(acc[mi][j][0] + vq0 + vd0 + bkf);
            o0.y = sigf(acc[mi][j][1] + vq0 + vd1 + bkf);
            o1.x = sigf(acc[mi][j][2] + vq1 + vd0 + bkf);
            o1.y = sigf(acc[mi][j][3] + vq1 + vd1 + bkf);
            *(float2*)&ob[(size_t)r0 * NN + col]       = o0;
            *(float2*)&ob[(size_t)(r0 + 8) * NN + col] = o1;
        }
    }
}

extern "C" void kernel_launch(void* const* d_in, const int* in_sizes, int n_in,
                              void* d_out, int out_size)
{
    (void)in_sizes; (void)n_in; (void)out_size;
    const float* q_em  = (const float*)d_in[0];
    const float* da_em = (const float*)d_in[1];
    const float* w     = (const float*)d_in[2];
    const float* V     = (const float*)d_in[3];
    const float* bias  = (const float*)d_in[4];
    float* out = (float*)d_out;

    cvt_q_kernel<<<4096, 256>>>((const float4*)q_em);
    cvt_w_kernel<<<1024, 256>>>((const float4*)w);
    cvt_daT_kernel<<<dim3(8, 8, 64), dim3(32, 8)>>>(da_em);
    vqvd_kernel<<<256, 128>>>(q_em, da_em, V);

    cudaFuncSetAttribute(ntn_mma_kernel, cudaFuncAttributeMaxDynamicSharedMemorySize, SMEM_TOTAL);
    ntn_mma_kernel<<<Bdim * Kdim * 2, 256, SMEM_TOTAL>>>(bias, out);
}

// round 10
// speedup vs baseline: 1.1946x; 1.1946x over previous
#include <cuda_runtime.h>
#include <cuda_bf16.h>
#include <cstdint>

#define Bdim 64
#define Kdim 16
#define NN   256
#define QT   64

// ---------------- pre-converted operand scratch (device globals) ----------------
__device__ __nv_bfloat16 g_qh[Bdim*NN*NN];   // [b][q][d] hi
__device__ __nv_bfloat16 g_ql[Bdim*NN*NN];
__device__ __nv_bfloat16 g_dh[Bdim*NN*NN];   // [b][d][a]  (DA transposed)
__device__ __nv_bfloat16 g_dl[Bdim*NN*NN];
__device__ __nv_bfloat16 g_wh[Kdim*NN*NN];   // [k][d][e]
__device__ __nv_bfloat16 g_wl[Kdim*NN*NN];
__device__ float g_vq[Bdim*Kdim*NN];
__device__ float g_vd[Bdim*Kdim*NN];

// ---------------- helpers ----------------
__device__ __forceinline__ void cvt2(float x, __nv_bfloat16& h, __nv_bfloat16& l) {
    h = __float2bfloat16(x);
    l = __float2bfloat16(x - __bfloat162float(h));
}
__device__ __forceinline__ uint32_t pack2(__nv_bfloat16 a, __nv_bfloat16 b) {
    __nv_bfloat162 v(a, b);
    return *(uint32_t*)&v;
}
__device__ __forceinline__ float sigf(float x) { return 1.0f / (1.0f + __expf(-x)); }

// ---------------- prep kernels ----------------
__global__ void cvt_q_kernel(const float4* __restrict__ q4) {
    int i = blockIdx.x * 256 + threadIdx.x;   // 4096 blocks
    float4 v = q4[i];
    __nv_bfloat16 h0,h1,h2,h3,l0,l1,l2,l3;
    cvt2(v.x,h0,l0); cvt2(v.y,h1,l1); cvt2(v.z,h2,l2); cvt2(v.w,h3,l3);
    ((uint2*)g_qh)[i] = make_uint2(pack2(h0,h1), pack2(h2,h3));
    ((uint2*)g_ql)[i] = make_uint2(pack2(l0,l1), pack2(l2,l3));
}
__global__ void cvt_w_kernel(const float4* __restrict__ w4) {
    int i = blockIdx.x * 256 + threadIdx.x;   // 1024 blocks
    float4 v = w4[i];
    __nv_bfloat16 h0,h1,h2,h3,l0,l1,l2,l3;
    cvt2(v.x,h0,l0); cvt2(v.y,h1,l1); cvt2(v.z,h2,l2); cvt2(v.w,h3,l3);
    ((uint2*)g_wh)[i] = make_uint2(pack2(h0,h1), pack2(h2,h3));
    ((uint2*)g_wl)[i] = make_uint2(pack2(l0,l1), pack2(l2,l3));
}
// DA: [b][a][d] fp32 -> [b][d][a] bf16 hi/lo
__global__ void cvt_daT_kernel(const float* __restrict__ da) {
    __shared__ float tile[32][33];
    int b = blockIdx.z, a0 = blockIdx.x * 32, d0 = blockIdx.y * 32;
    int tx = threadIdx.x, ty = threadIdx.y;   // 32 x 8
    const float* src = da + ((size_t)b * NN + a0) * NN + d0;
    #pragma unroll
    for (int i = 0; i < 4; i++)
        tile[ty + 8*i][tx] = src[(size_t)(ty + 8*i) * NN + tx];
    __syncthreads();
    #pragma unroll
    for (int i = 0; i < 4; i++) {
        int dl = ty + 8*i;
        float v = tile[tx][dl];
        __nv_bfloat16 h, l; cvt2(v, h, l);
        size_t o = ((size_t)b * NN + d0 + dl) * NN + a0 + tx;
        g_dh[o] = h; g_dl[o] = l;
    }
}
// vq/vd: grid 1024 = b(64) x which(2) x rowgroup(8); block 128 = 32 rows x 4 k-splits
__global__ void vqvd_kernel(const float* __restrict__ q_em, const float* __restrict__ da_em,
                            const float* __restrict__ V) {
    __shared__ float Vs[16 * NN];
    int bx = blockIdx.x;
    int b = bx >> 4, which = (bx >> 3) & 1, rg = bx & 7;
    int t = threadIdx.x;
    #pragma unroll
    for (int i = 0; i < 32; i++) {
        int idx = i * 128 + t, k = idx >> 8, d = idx & 255;
        Vs[idx] = V[k * 512 + which * 256 + d];
    }
    __syncthreads();
    int row = rg * 32 + (t >> 2);
    int ks  = (t & 3) * 4;
    const float* src = (which ? da_em : q_em) + (size_t)(b * NN + row) * NN;
    float* dst = (which ? g_vd : g_vq);
    float acc[4] = {0.f, 0.f, 0.f, 0.f};
    const float4* r4 = (const float4*)src;
    const float4* Vs4 = (const float4*)Vs;
    #pragma unroll 4
    for (int d4 = 0; d4 < 64; d4++) {
        float4 x = r4[d4];
        #pragma unroll
        for (int j = 0; j < 4; j++) {
            float4 v = Vs4[(ks + j) * 64 + d4];
            acc[j] += x.x*v.x + x.y*v.y + x.z*v.z + x.w*v.w;
        }
    }
    #pragma unroll
    for (int j = 0; j < 4; j++) dst[(b * 16 + ks + j) * NN + row] = acc[j];
}

// ---------------- mma/ldsm wrappers ----------------
__device__ __forceinline__ void ldsm_x4(unsigned* r, uint32_t addr) {
    asm volatile("ldmatrix.sync.aligned.m8n8.x4.shared.b16 {%0,%1,%2,%3}, [%4];"
                 : "=r"(r[0]), "=r"(r[1]), "=r"(r[2]), "=r"(r[3]) : "r"(addr));
}
__device__ __forceinline__ void ldsm_x4t(unsigned* r, uint32_t addr) {
    asm volatile("ldmatrix.sync.aligned.m8n8.x4.trans.shared.b16 {%0,%1,%2,%3}, [%4];"
                 : "=r"(r[0]), "=r"(r[1]), "=r"(r[2]), "=r"(r[3]) : "r"(addr));
}
__device__ __forceinline__ void mma_bf16(float* c, const unsigned* a, unsigned b0, unsigned b1) {
    asm volatile("mma.sync.aligned.m16n8k16.row.col.f32.bf16.bf16.f32 "
                 "{%0,%1,%2,%3}, {%4,%5,%6,%7}, {%8,%9}, {%0,%1,%2,%3};"
                 : "+f"(c[0]), "+f"(c[1]), "+f"(c[2]), "+f"(c[3])
                 : "r"(a[0]), "r"(a[1]), "r"(a[2]), "r"(a[3]), "r"(b0), "r"(b1));
}
__device__ __forceinline__ void cpa16(uint32_t dst, const void* src) {
    asm volatile("cp.async.cg.shared.global [%0], [%1], 16;" :: "r"(dst), "l"(src) : "memory");
}
#define CP_COMMIT() asm volatile("cp.async.commit_group;" ::: "memory")
#define CP_WAIT(n)  asm volatile("cp.async.wait_group %0;" :: "n"(n) : "memory")

// ---------------- SMEM layout (bytes) ----------------
#define TS_H 0
#define TS_L 32768
#define S1_OFF 65536
#define S1_STRIDE 23552
#define QS_H 0
#define QS_L 3072
#define WS_H 6144
#define WS_L 14592
#define S2_OFF 65536               // alias of S1 region
#define S2_STRIDE 17408
#define DA_H 0
#define DA_L 8448
#define VQ_OFF (S1_OFF + 2*S1_STRIDE)   // 112640
#define VD_OFF (VQ_OFF + 256)
#define SMEM_TOTAL (VD_OFF + 1024)      // 113920

#define QP 24    // Q slab pitch (halves)
#define WP 264   // W / DA slab pitch (halves)

// Ts swizzled address: row r (0..63), 16B-unit u (0..31)
__device__ __forceinline__ uint32_t ts_addr(uint32_t base, int r, int u) {
    return base + (uint32_t)(r * 512) + (uint32_t)(((u ^ (r & 7)) << 4));
}

// ---------------- cp.async slab issuers ----------------
__device__ __forceinline__ void s1_issue(uint32_t buf,
    const __nv_bfloat16* qh, const __nv_bfloat16* ql,
    const __nv_bfloat16* wh, const __nv_bfloat16* wl, int d0, int t)
{
    {   // Q slab: 64 rows x 16 halves, hi+lo -> 256 tasks
        int arr = t >> 7, idx = t & 127, row = idx >> 1, ch = idx & 1;
        uint32_t dst = buf + (arr ? QS_L : QS_H) + (uint32_t)(row * QP + ch * 8) * 2;
        const __nv_bfloat16* src = (arr ? ql : qh) + (size_t)row * NN + d0 + ch * 8;
        cpa16(dst, src);
    }
    // W slab: 16 rows x 256 halves, hi+lo -> 1024 tasks
    #pragma unroll
    for (int i = 0; i < 4; i++) {
        int task = i * 256 + t;
        int arr = task >> 9, idx = task & 511, row = idx >> 5, ch = idx & 31;
        uint32_t dst = buf + (arr ? WS_L : WS_H) + (uint32_t)(row * WP + ch * 8) * 2;
        const __nv_bfloat16* src = (arr ? wl : wh) + (size_t)(d0 + row) * NN + ch * 8;
        cpa16(dst, src);
    }
    CP_COMMIT();
}
__device__ __forceinline__ void s2_issue(uint32_t buf,
    const __nv_bfloat16* dth, const __nv_bfloat16* dtl, int e0, int t)
{
    // DA^T slab: 16 rows (d) x 256 halves (a), hi+lo -> 1024 tasks
    #pragma unroll
    for (int i = 0; i < 4; i++) {
        int task = i * 256 + t;
        int arr = task >> 9, idx = task & 511, row = idx >> 5, ch = idx & 31;
        uint32_t dst = buf + (arr ? DA_L : DA_H) + (uint32_t)(row * WP + ch * 8) * 2;
        const __nv_bfloat16* src = (arr ? dtl : dth) + (size_t)(e0 + row) * NN + ch * 8;
        cpa16(dst, src);
    }
    CP_COMMIT();
}

// ---------------- main kernel ----------------
__global__ void __launch_bounds__(256, 2)
ntn_mma_kernel(const float* __restrict__ bias, float* __restrict__ out)
{
    extern __shared__ char sm[];
    const uint32_t smb = (uint32_t)__cvta_generic_to_shared(sm);
    float* vq = (float*)(sm + VQ_OFF);
    float* vd = (float*)(sm + VD_OFF);

    const int t  = threadIdx.x;
    const int bx = blockIdx.x;
    const int qt = bx & 3;
    const int k  = (bx >> 2) & 15;
    const int b  = bx >> 6;
    const int q0 = qt * QT;
    const int bk = b * 16 + k;

    const int warp = t >> 5;
    const int lane = t & 31;
    const int wq   = warp >> 2;   // 0..1: 32 q-rows each
    const int we   = warp & 3;    // 0..3: 64 cols each
    const int grp  = lane >> 2;
    const int tig  = lane & 3;

    // vq/vd from precomputed globals
    if (t < QT) vq[t] = g_vq[bk * NN + q0 + t];
    vd[t] = g_vd[bk * NN + t];

    const __nv_bfloat16* qh_p = g_qh + ((size_t)b * NN + q0) * NN;
    const __nv_bfloat16* ql_p = g_ql + ((size_t)b * NN + q0) * NN;
    const __nv_bfloat16* wh_p = g_wh + (size_t)k * NN * NN;
    const __nv_bfloat16* wl_p = g_wl + (size_t)k * NN * NN;
    const __nv_bfloat16* dh_p = g_dh + (size_t)b * NN * NN;
    const __nv_bfloat16* dl_p = g_dl + (size_t)b * NN * NN;

    float acc[2][8][4];
    #pragma unroll
    for (int m = 0; m < 2; m++)
        #pragma unroll
        for (int j = 0; j < 8; j++)
            #pragma unroll
            for (int c = 0; c < 4; c++) acc[m][j][c] = 0.f;

    // ldmatrix address components
    const int a_row  = wq * 32 + (lane & 15);
    const int a_cu   = lane >> 4;            // k-half selector
    const int bw_row = lane & 15;            // B (trans): d row

    // =============== Stage 1: T[64][256] = Q @ W_k ===============
    s1_issue(smb + S1_OFF, qh_p, ql_p, wh_p, wl_p, 0, t);

    #pragma unroll 1
    for (int it = 0; it < 16; it++) {
        CP_WAIT(0);                    // slab it resident (issued last iter)
        __syncthreads();               // compute(it-1) done everywhere
        if (it + 1 < 16)               // safe: its buffer was last read at compute(it-1)
            s1_issue(smb + S1_OFF + ((it + 1) & 1) * S1_STRIDE,
                     qh_p, ql_p, wh_p, wl_p, (it + 1) * 16, t);
        uint32_t cur = smb + S1_OFF + (it & 1) * S1_STRIDE;

        unsigned ah[2][4], al[2][4];
        uint32_t qa = cur + QS_H + (uint32_t)(a_row * QP + a_cu * 8) * 2;
        ldsm_x4(ah[0], qa);
        ldsm_x4(ah[1], qa + 16 * QP * 2);
        qa = cur + QS_L + (uint32_t)(a_row * QP + a_cu * 8) * 2;
        ldsm_x4(al[0], qa);
        ldsm_x4(al[1], qa + 16 * QP * 2);

        #pragma unroll
        for (int n2 = 0; n2 < 4; n2++) {
            uint32_t eoff = (uint32_t)(bw_row * WP + we * 64 + n2 * 16 + a_cu * 8) * 2;
            unsigned bh[4], bl[4];
            ldsm_x4t(bh, cur + WS_H + eoff);
            ldsm_x4t(bl, cur + WS_L + eoff);
            #pragma unroll
            for (int m = 0; m < 2; m++) {
                float* c0 = acc[m][2 * n2];
                float* c1 = acc[m][2 * n2 + 1];
                mma_bf16(c0, ah[m], bh[0], bh[1]);
                mma_bf16(c0, ah[m], bl[0], bl[1]);
                mma_bf16(c0, al[m], bh[0], bh[1]);
                mma_bf16(c1, ah[m], bh[2], bh[3]);
                mma_bf16(c1, ah[m], bl[2], bl[3]);
                mma_bf16(c1, al[m], bh[2], bh[3]);
            }
        }
    }

    // first DA slab into S2 buf0: disjoint from S1 buf1 (being read by compute(15));
    // overlaps S1 buf0, whose last readers (compute(14)) are behind the it=15 barrier.
    s2_issue(smb + S2_OFF, dh_p, dl_p, 0, t);

    // -------- write T to swizzled SMEM as bf16 hi/lo --------
    #pragma unroll
    for (int m = 0; m < 2; m++) {
        int r0 = wq * 32 + m * 16 + grp;
        #pragma unroll
        for (int j = 0; j < 8; j++) {
            int u = we * 8 + j;            // 16B unit of col
            __nv_bfloat16 h0, l0, h1, l1, h2, l2, h3, l3;
            cvt2(acc[m][j][0], h0, l0); cvt2(acc[m][j][1], h1, l1);
            cvt2(acc[m][j][2], h2, l2); cvt2(acc[m][j][3], h3, l3);
            uint32_t a0 = ts_addr(smb + TS_H, r0, u) + tig * 4;
            uint32_t a1 = ts_addr(smb + TS_H, r0 + 8, u) + tig * 4;
            uint32_t b0 = ts_addr(smb + TS_L, r0, u) + tig * 4;
            uint32_t b1 = ts_addr(smb + TS_L, r0 + 8, u) + tig * 4;
            uint32_t v;
            v = pack2(h0, h1); asm volatile("st.shared.b32 [%0], %1;" :: "r"(a0), "r"(v) : "memory");
            v = pack2(h2, h3); asm volatile("st.shared.b32 [%0], %1;" :: "r"(a1), "r"(v) : "memory");
            v = pack2(l0, l1); asm volatile("st.shared.b32 [%0], %1;" :: "r"(b0), "r"(v) : "memory");
            v = pack2(l2, l3); asm volatile("st.shared.b32 [%0], %1;" :: "r"(b1), "r"(v) : "memory");
        }
    }
    __syncthreads();   // Ts visible to all warps (enables hoisted A-ldsm below)

    // =============== Stage 2: OUT = T @ DA^T ===============
    #pragma unroll
    for (int m = 0; m < 2; m++)
        #pragma unroll
        for (int j = 0; j < 8; j++)
            #pragma unroll
            for (int c = 0; c < 4; c++) acc[m][j][c] = 0.f;

    #pragma unroll 1
    for (int it = 0; it < 16; it++) {
        // A frags from stable Ts region — hoisted above the wait to hide LDS latency
        unsigned ah[2][4], al[2][4];
        int u = it * 2 + a_cu;
        ldsm_x4(ah[0], ts_addr(smb + TS_H, a_row, u));
        ldsm_x4(ah[1], ts_addr(smb + TS_H, a_row + 16, u));
        ldsm_x4(al[0], ts_addr(smb + TS_L, a_row, u));
        ldsm_x4(al[1], ts_addr(smb + TS_L, a_row + 16, u));

        CP_WAIT(0);
        __syncthreads();
        if (it + 1 < 16)
            s2_issue(smb + S2_OFF + ((it + 1) & 1) * S2_STRIDE, dh_p, dl_p, (it + 1) * 16, t);
        uint32_t cur = smb + S2_OFF + (it & 1) * S2_STRIDE;

        #pragma unroll
        for (int n2 = 0; n2 < 4; n2++) {
            uint32_t aoff = (uint32_t)(bw_row * WP + we * 64 + n2 * 16 + a_cu * 8) * 2;
            unsigned bh[4], bl[4];
            ldsm_x4t(bh, cur + DA_H + aoff);
            ldsm_x4t(bl, cur + DA_L + aoff);
            #pragma unroll
            for (int m = 0; m < 2; m++) {
                float* c0 = acc[m][2 * n2];
                float* c1 = acc[m][2 * n2 + 1];
                mma_bf16(c0, ah[m], bh[0], bh[1]);
                mma_bf16(c0, ah[m], bl[0], bl[1]);
                mma_bf16(c0, al[m], bh[0], bh[1]);
                mma_bf16(c1, ah[m], bh[2], bh[3]);
                mma_bf16(c1, ah[m], bl[2], bl[3]);
                mma_bf16(c1, al[m], bh[2], bh[3]);
            }
        }
    }

    // =============== Epilogue: + vq + vd + bias, sigmoid ===============
    const float bkf = bias[k];
    float* ob = out + (((size_t)b * Kdim + k) * NN + q0) * (size_t)NN;
    #pragma unroll
    for (int m = 0; m < 2; m++) {
        int r0 = wq * 32 + m * 16 + grp;
        float vq0 = vq[r0], vq1 = vq[r0 + 8];
        #pragma unroll
        for (int j = 0; j < 8; j++) {
            int col = we * 64 + j * 8 + tig * 2;
            float vd0 = vd[col], vd1 = vd[col + 1];
            float2 o0, o1;
            o0.x = sigf(acc[m][j][0] + vq0 + vd0 + bkf);
            o0.y = sigf(acc[m][j][1] + vq0 + vd1 + bkf);
            o1.x = sigf(acc[m][j][2] + vq1 + vd0 + bkf);
            o1.y = sigf(acc[m][j][3] + vq1 + vd1 + bkf);
            *(float2*)&ob[(size_t)r0 * NN + col]       = o0;
            *(float2*)&ob[(size_t)(r0 + 8) * NN + col] = o1;
        }
    }
}

extern "C" void kernel_launch(void* const* d_in, const int* in_sizes, int n_in,
                              void* d_out, int out_size)
{
    (void)in_sizes; (void)n_in; (void)out_size;
    const float* q_em  = (const float*)d_in[0];
    const float* da_em = (const float*)d_in[1];
    const float* w     = (const float*)d_in[2];
    const float* V     = (const float*)d_in[3];
    const float* bias  = (const float*)d_in[4];
    float* out = (float*)d_out;

    cvt_q_kernel<<<4096, 256>>>((const float4*)q_em);
    cvt_w_kernel<<<1024, 256>>>((const float4*)w);
    cvt_daT_kernel<<<dim3(8, 8, 64), dim3(32, 8)>>>(da_em);
    vqvd_kernel<<<1024, 128>>>(q_em, da_em, V);

    cudaFuncSetAttribute(ntn_mma_kernel, cudaFuncAttributeMaxDynamicSharedMemorySize, SMEM_TOTAL);
    ntn_mma_kernel<<<4096, 256, SMEM_TOTAL>>>(bias, out);
}

// round 11
// speedup vs baseline: 1.2761x; 1.0683x over previous
#include <cuda_runtime.h>
#include <cuda_bf16.h>
#include <cstdint>

#define Bdim 64
#define Kdim 16
#define NN   256
#define QT   64

// ---------------- pre-converted operand scratch (device globals) ----------------
__device__ __nv_bfloat16 g_qh[Bdim*NN*NN];   // [b][q][d] hi
__device__ __nv_bfloat16 g_ql[Bdim*NN*NN];
__device__ __nv_bfloat16 g_dh[Bdim*NN*NN];   // [b][d][a]  (DA transposed)
__device__ __nv_bfloat16 g_dl[Bdim*NN*NN];
__device__ __nv_bfloat16 g_wh[Kdim*NN*NN];   // [k][d][e]
__device__ __nv_bfloat16 g_wl[Kdim*NN*NN];
__device__ float g_vq[Bdim*Kdim*NN];
__device__ float g_vd[Bdim*Kdim*NN];

// ---------------- helpers ----------------
__device__ __forceinline__ void cvt2(float x, __nv_bfloat16& h, __nv_bfloat16& l) {
    h = __float2bfloat16(x);
    l = __float2bfloat16(x - __bfloat162float(h));
}
__device__ __forceinline__ uint32_t pack2(__nv_bfloat16 a, __nv_bfloat16 b) {
    __nv_bfloat162 v(a, b);
    return *(uint32_t*)&v;
}
__device__ __forceinline__ float sigf(float x) { return 1.0f / (1.0f + __expf(-x)); }

// ---------------- prep kernels ----------------
__global__ void cvt_q_kernel(const float4* __restrict__ q4) {
    int i = blockIdx.x * 256 + threadIdx.x;   // 4096 blocks
    float4 v = q4[i];
    __nv_bfloat16 h0,h1,h2,h3,l0,l1,l2,l3;
    cvt2(v.x,h0,l0); cvt2(v.y,h1,l1); cvt2(v.z,h2,l2); cvt2(v.w,h3,l3);
    ((uint2*)g_qh)[i] = make_uint2(pack2(h0,h1), pack2(h2,h3));
    ((uint2*)g_ql)[i] = make_uint2(pack2(l0,l1), pack2(l2,l3));
}
__global__ void cvt_w_kernel(const float4* __restrict__ w4) {
    int i = blockIdx.x * 256 + threadIdx.x;   // 1024 blocks
    float4 v = w4[i];
    __nv_bfloat16 h0,h1,h2,h3,l0,l1,l2,l3;
    cvt2(v.x,h0,l0); cvt2(v.y,h1,l1); cvt2(v.z,h2,l2); cvt2(v.w,h3,l3);
    ((uint2*)g_wh)[i] = make_uint2(pack2(h0,h1), pack2(h2,h3));
    ((uint2*)g_wl)[i] = make_uint2(pack2(l0,l1), pack2(l2,l3));
}
// DA: [b][a][d] fp32 -> [b][d][a] bf16 hi/lo
__global__ void cvt_daT_kernel(const float* __restrict__ da) {
    __shared__ float tile[32][33];
    int b = blockIdx.z, a0 = blockIdx.x * 32, d0 = blockIdx.y * 32;
    int tx = threadIdx.x, ty = threadIdx.y;   // 32 x 8
    const float* src = da + ((size_t)b * NN + a0) * NN + d0;
    #pragma unroll
    for (int i = 0; i < 4; i++)
        tile[ty + 8*i][tx] = src[(size_t)(ty + 8*i) * NN + tx];
    __syncthreads();
    #pragma unroll
    for (int i = 0; i < 4; i++) {
        int dl = ty + 8*i;
        float v = tile[tx][dl];
        __nv_bfloat16 h, l; cvt2(v, h, l);
        size_t o = ((size_t)b * NN + d0 + dl) * NN + a0 + tx;
        g_dh[o] = h; g_dl[o] = l;
    }
}
// vqvd: proven R7 config — grid 128 = b(64) x which(2), block 256, one row/thread
__global__ void vqvd_kernel(const float* __restrict__ q_em, const float* __restrict__ da_em,
                            const float* __restrict__ V) {
    __shared__ float Vs[16 * NN];
    int b = blockIdx.x >> 1, which = blockIdx.x & 1;
    int t = threadIdx.x;
    #pragma unroll
    for (int i = 0; i < 16; i++) {
        int idx = i * 256 + t, k = idx >> 8, d = idx & 255;
        Vs[idx] = V[k * 512 + which * 256 + d];
    }
    __syncthreads();
    const float* src = (which ? da_em : q_em) + (size_t)(b * NN + t) * NN;
    float* dst = (which ? g_vd : g_vq);
    float acc[16];
    #pragma unroll
    for (int k = 0; k < 16; k++) acc[k] = 0.f;
    const float4* row = (const float4*)src;
    const float4* Vs4 = (const float4*)Vs;
    for (int d4 = 0; d4 < 64; d4++) {
        float4 x = row[d4];
        #pragma unroll
        for (int k = 0; k < 16; k++) {
            float4 v = Vs4[k * 64 + d4];
            acc[k] += x.x*v.x + x.y*v.y + x.z*v.z + x.w*v.w;
        }
    }
    #pragma unroll
    for (int k = 0; k < 16; k++) dst[(b * 16 + k) * NN + t] = acc[k];
}

// ---------------- mma/ldsm wrappers ----------------
__device__ __forceinline__ void ldsm_x4(unsigned* r, uint32_t addr) {
    asm volatile("ldmatrix.sync.aligned.m8n8.x4.shared.b16 {%0,%1,%2,%3}, [%4];"
                 : "=r"(r[0]), "=r"(r[1]), "=r"(r[2]), "=r"(r[3]) : "r"(addr));
}
__device__ __forceinline__ void ldsm_x4t(unsigned* r, uint32_t addr) {
    asm volatile("ldmatrix.sync.aligned.m8n8.x4.trans.shared.b16 {%0,%1,%2,%3}, [%4];"
                 : "=r"(r[0]), "=r"(r[1]), "=r"(r[2]), "=r"(r[3]) : "r"(addr));
}
__device__ __forceinline__ void mma_bf16(float* c, const unsigned* a, unsigned b0, unsigned b1) {
    asm volatile("mma.sync.aligned.m16n8k16.row.col.f32.bf16.bf16.f32 "
                 "{%0,%1,%2,%3}, {%4,%5,%6,%7}, {%8,%9}, {%0,%1,%2,%3};"
                 : "+f"(c[0]), "+f"(c[1]), "+f"(c[2]), "+f"(c[3])
                 : "r"(a[0]), "r"(a[1]), "r"(a[2]), "r"(a[3]), "r"(b0), "r"(b1));
}
__device__ __forceinline__ void cpa16(uint32_t dst, const void* src) {
    asm volatile("cp.async.cg.shared.global [%0], [%1], 16;" :: "r"(dst), "l"(src) : "memory");
}
#define CP_COMMIT() asm volatile("cp.async.commit_group;" ::: "memory")
#define CP_WAIT(n)  asm volatile("cp.async.wait_group %0;" :: "n"(n) : "memory")

// ---------------- SMEM layout (bytes) ----------------
#define TS_H 0
#define TS_L 32768
#define S1_OFF 65536
#define S1_STRIDE 23552
#define QS_H 0
#define QS_L 3072
#define WS_H 6144
#define WS_L 14592
#define S2_OFF 65536               // alias of S1 region
#define S2_STRIDE 17408
#define DA_H 0
#define DA_L 8448
#define VQ_OFF (S1_OFF + 2*S1_STRIDE)   // 112640
#define VD_OFF (VQ_OFF + 256)
#define SMEM_TOTAL (VD_OFF + 1024)      // 113920

#define QP 24    // Q slab pitch (halves)
#define WP 264   // W / DA slab pitch (halves)

// Ts swizzled address: row r (0..63), 16B-unit u (0..31)
__device__ __forceinline__ uint32_t ts_addr(uint32_t base, int r, int u) {
    return base + (uint32_t)(r * 512) + (uint32_t)(((u ^ (r & 7)) << 4));
}

// ---------------- cp.async slab issuers ----------------
__device__ __forceinline__ void s1_issue(uint32_t buf,
    const __nv_bfloat16* qh, const __nv_bfloat16* ql,
    const __nv_bfloat16* wh, const __nv_bfloat16* wl, int d0, int t)
{
    {   // Q slab: 64 rows x 16 halves, hi+lo -> 256 tasks
        int arr = t >> 7, idx = t & 127, row = idx >> 1, ch = idx & 1;
        uint32_t dst = buf + (arr ? QS_L : QS_H) + (uint32_t)(row * QP + ch * 8) * 2;
        const __nv_bfloat16* src = (arr ? ql : qh) + (size_t)row * NN + d0 + ch * 8;
        cpa16(dst, src);
    }
    // W slab: 16 rows x 256 halves, hi+lo -> 1024 tasks
    #pragma unroll
    for (int i = 0; i < 4; i++) {
        int task = i * 256 + t;
        int arr = task >> 9, idx = task & 511, row = idx >> 5, ch = idx & 31;
        uint32_t dst = buf + (arr ? WS_L : WS_H) + (uint32_t)(row * WP + ch * 8) * 2;
        const __nv_bfloat16* src = (arr ? wl : wh) + (size_t)(d0 + row) * NN + ch * 8;
        cpa16(dst, src);
    }
    CP_COMMIT();
}
__device__ __forceinline__ void s2_issue(uint32_t buf,
    const __nv_bfloat16* dth, const __nv_bfloat16* dtl, int e0, int t)
{
    // DA^T slab: 16 rows (d) x 256 halves (a), hi+lo -> 1024 tasks
    #pragma unroll
    for (int i = 0; i < 4; i++) {
        int task = i * 256 + t;
        int arr = task >> 9, idx = task & 511, row = idx >> 5, ch = idx & 31;
        uint32_t dst = buf + (arr ? DA_L : DA_H) + (uint32_t)(row * WP + ch * 8) * 2;
        const __nv_bfloat16* src = (arr ? dtl : dth) + (size_t)(e0 + row) * NN + ch * 8;
        cpa16(dst, src);
    }
    CP_COMMIT();
}

// ---------------- main kernel ----------------
__global__ void __launch_bounds__(256, 2)
ntn_mma_kernel(const float* __restrict__ bias, float* __restrict__ out)
{
    extern __shared__ char sm[];
    const uint32_t smb = (uint32_t)__cvta_generic_to_shared(sm);
    float* vq = (float*)(sm + VQ_OFF);
    float* vd = (float*)(sm + VD_OFF);

    const int t  = threadIdx.x;
    const int bx = blockIdx.x;
    const int qt = bx & 3;
    const int k  = (bx >> 2) & 15;
    const int b  = bx >> 6;
    const int q0 = qt * QT;
    const int bk = b * 16 + k;

    const int warp = t >> 5;
    const int lane = t & 31;
    const int wq   = warp >> 2;   // 0..1: 32 q-rows each
    const int we   = warp & 3;    // 0..3: 64 cols each
    const int grp  = lane >> 2;
    const int tig  = lane & 3;

    // vq/vd from precomputed globals
    if (t < QT) vq[t] = g_vq[bk * NN + q0 + t];
    vd[t] = g_vd[bk * NN + t];

    const __nv_bfloat16* qh_p = g_qh + ((size_t)b * NN + q0) * NN;
    const __nv_bfloat16* ql_p = g_ql + ((size_t)b * NN + q0) * NN;
    const __nv_bfloat16* wh_p = g_wh + (size_t)k * NN * NN;
    const __nv_bfloat16* wl_p = g_wl + (size_t)k * NN * NN;
    const __nv_bfloat16* dh_p = g_dh + (size_t)b * NN * NN;
    const __nv_bfloat16* dl_p = g_dl + (size_t)b * NN * NN;

    float acc[2][8][4];
    #pragma unroll
    for (int m = 0; m < 2; m++)
        #pragma unroll
        for (int j = 0; j < 8; j++)
            #pragma unroll
            for (int c = 0; c < 4; c++) acc[m][j][c] = 0.f;

    // ldmatrix address components
    const int a_row  = wq * 32 + (lane & 15);
    const int a_cu   = lane >> 4;            // k-half selector
    const int bw_row = lane & 15;            // B (trans): d row

    // =============== Stage 1: T[64][256] = Q @ W_k ===============
    s1_issue(smb + S1_OFF, qh_p, ql_p, wh_p, wl_p, 0, t);

    #pragma unroll 1
    for (int it = 0; it < 16; it++) {
        CP_WAIT(0);                    // slab it resident (issued last iter)
        __syncthreads();               // compute(it-1) done everywhere
        if (it + 1 < 16)               // safe: its buffer was last read at compute(it-1)
            s1_issue(smb + S1_OFF + ((it + 1) & 1) * S1_STRIDE,
                     qh_p, ql_p, wh_p, wl_p, (it + 1) * 16, t);
        uint32_t cur = smb + S1_OFF + (it & 1) * S1_STRIDE;

        unsigned ah[2][4], al[2][4];
        uint32_t qa = cur + QS_H + (uint32_t)(a_row * QP + a_cu * 8) * 2;
        ldsm_x4(ah[0], qa);
        ldsm_x4(ah[1], qa + 16 * QP * 2);
        qa = cur + QS_L + (uint32_t)(a_row * QP + a_cu * 8) * 2;
        ldsm_x4(al[0], qa);
        ldsm_x4(al[1], qa + 16 * QP * 2);

        #pragma unroll
        for (int n2 = 0; n2 < 4; n2++) {
            uint32_t eoff = (uint32_t)(bw_row * WP + we * 64 + n2 * 16 + a_cu * 8) * 2;
            unsigned bh[4], bl[4];
            ldsm_x4t(bh, cur + WS_H + eoff);
            ldsm_x4t(bl, cur + WS_L + eoff);
            #pragma unroll
            for (int m = 0; m < 2; m++) {
                float* c0 = acc[m][2 * n2];
                float* c1 = acc[m][2 * n2 + 1];
                mma_bf16(c0, ah[m], bh[0], bh[1]);
                mma_bf16(c0, ah[m], bl[0], bl[1]);
                mma_bf16(c0, al[m], bh[0], bh[1]);
                mma_bf16(c1, ah[m], bh[2], bh[3]);
                mma_bf16(c1, ah[m], bl[2], bl[3]);
                mma_bf16(c1, al[m], bh[2], bh[3]);
            }
        }
    }

    // first DA slab into S2 buf0: disjoint from S1 buf1 (being read by compute(15));
    // overlaps S1 buf0, whose last readers (compute(14)) are behind the it=15 barrier.
    s2_issue(smb + S2_OFF, dh_p, dl_p, 0, t);

    // -------- write T to swizzled SMEM as bf16 hi/lo --------
    #pragma unroll
    for (int m = 0; m < 2; m++) {
        int r0 = wq * 32 + m * 16 + grp;
        #pragma unroll
        for (int j = 0; j < 8; j++) {
            int u = we * 8 + j;            // 16B unit of col
            __nv_bfloat16 h0, l0, h1, l1, h2, l2, h3, l3;
            cvt2(acc[m][j][0], h0, l0); cvt2(acc[m][j][1], h1, l1);
            cvt2(acc[m][j][2], h2, l2); cvt2(acc[m][j][3], h3, l3);
            uint32_t a0 = ts_addr(smb + TS_H, r0, u) + tig * 4;
            uint32_t a1 = ts_addr(smb + TS_H, r0 + 8, u) + tig * 4;
            uint32_t b0 = ts_addr(smb + TS_L, r0, u) + tig * 4;
            uint32_t b1 = ts_addr(smb + TS_L, r0 + 8, u) + tig * 4;
            uint32_t v;
            v = pack2(h0, h1); asm volatile("st.shared.b32 [%0], %1;" :: "r"(a0), "r"(v) : "memory");
            v = pack2(h2, h3); asm volatile("st.shared.b32 [%0], %1;" :: "r"(a1), "r"(v) : "memory");
            v = pack2(l0, l1); asm volatile("st.shared.b32 [%0], %1;" :: "r"(b0), "r"(v) : "memory");
            v = pack2(l2, l3); asm volatile("st.shared.b32 [%0], %1;" :: "r"(b1), "r"(v) : "memory");
        }
    }
    __syncthreads();   // Ts visible to all warps (enables hoisted A-ldsm below)

    // =============== Stage 2: OUT = T @ DA^T ===============
    #pragma unroll
    for (int m = 0; m < 2; m++)
        #pragma unroll
        for (int j = 0; j < 8; j++)
            #pragma unroll
            for (int c = 0; c < 4; c++) acc[m][j][c] = 0.f;

    #pragma unroll 1
    for (int it = 0; it < 16; it++) {
        // A frags from stable Ts region — hoisted above the wait to hide LDS latency
        unsigned ah[2][4], al[2][4];
        int u = it * 2 + a_cu;
        ldsm_x4(ah[0], ts_addr(smb + TS_H, a_row, u));
        ldsm_x4(ah[1], ts_addr(smb + TS_H, a_row + 16, u));
        ldsm_x4(al[0], ts_addr(smb + TS_L, a_row, u));
        ldsm_x4(al[1], ts_addr(smb + TS_L, a_row + 16, u));

        CP_WAIT(0);
        __syncthreads();
        if (it + 1 < 16)
            s2_issue(smb + S2_OFF + ((it + 1) & 1) * S2_STRIDE, dh_p, dl_p, (it + 1) * 16, t);
        uint32_t cur = smb + S2_OFF + (it & 1) * S2_STRIDE;

        #pragma unroll
        for (int n2 = 0; n2 < 4; n2++) {
            uint32_t aoff = (uint32_t)(bw_row * WP + we * 64 + n2 * 16 + a_cu * 8) * 2;
            unsigned bh[4], bl[4];
            ldsm_x4t(bh, cur + DA_H + aoff);
            ldsm_x4t(bl, cur + DA_L + aoff);
            #pragma unroll
            for (int m = 0; m < 2; m++) {
                float* c0 = acc[m][2 * n2];
                float* c1 = acc[m][2 * n2 + 1];
                mma_bf16(c0, ah[m], bh[0], bh[1]);
                mma_bf16(c0, ah[m], bl[0], bl[1]);
                mma_bf16(c0, al[m], bh[0], bh[1]);
                mma_bf16(c1, ah[m], bh[2], bh[3]);
                mma_bf16(c1, ah[m], bl[2], bl[3]);
                mma_bf16(c1, al[m], bh[2], bh[3]);
            }
        }
    }

    // =============== Epilogue: + vq + vd + bias, sigmoid ===============
    const float bkf = bias[k];
    float* ob = out + (((size_t)b * Kdim + k) * NN + q0) * (size_t)NN;
    #pragma unroll
    for (int m = 0; m < 2; m++) {
        int r0 = wq * 32 + m * 16 + grp;
        float vq0 = vq[r0], vq1 = vq[r0 + 8];
        #pragma unroll
        for (int j = 0; j < 8; j++) {
            int col = we * 64 + j * 8 + tig * 2;
            float vd0 = vd[col], vd1 = vd[col + 1];
            float2 o0, o1;
            o0.x = sigf(acc[m][j][0] + vq0 + vd0 + bkf);
            o0.y = sigf(acc[m][j][1] + vq0 + vd1 + bkf);
            o1.x = sigf(acc[m][j][2] + vq1 + vd0 + bkf);
            o1.y = sigf(acc[m][j][3] + vq1 + vd1 + bkf);
            *(float2*)&ob[(size_t)r0 * NN + col]       = o0;
            *(float2*)&ob[(size_t)(r0 + 8) * NN + col] = o1;
        }
    }
}

extern "C" void kernel_launch(void* const* d_in, const int* in_sizes, int n_in,
                              void* d_out, int out_size)
{
    (void)in_sizes; (void)n_in; (void)out_size;
    const float* q_em  = (const float*)d_in[0];
    const float* da_em = (const float*)d_in[1];
    const float* w     = (const float*)d_in[2];
    const float* V     = (const float*)d_in[3];
    const float* bias  = (const float*)d_in[4];
    float* out = (float*)d_out;

    cvt_q_kernel<<<4096, 256>>>((const float4*)q_em);
    cvt_w_kernel<<<1024, 256>>>((const float4*)w);
    cvt_daT_kernel<<<dim3(8, 8, 64), dim3(32, 8)>>>(da_em);
    vqvd_kernel<<<128, 256>>>(q_em, da_em, V);

    cudaFuncSetAttribute(ntn_mma_kernel, cudaFuncAttributeMaxDynamicSharedMemorySize, SMEM_TOTAL);
    ntn_mma_kernel<<<4096, 256, SMEM_TOTAL>>>(bias, out);
}

// round 12
// speedup vs baseline: 1.2931x; 1.0133x over previous
#include <cuda_runtime.h>
#include <cuda_bf16.h>
#include <cstdint>

#define Bdim 64
#define Kdim 16
#define NN   256
#define QT   64

// ---------------- pre-converted operand scratch (device globals) ----------------
__device__ __nv_bfloat16 g_qh[Bdim*NN*NN];   // [b][q][d] hi
__device__ __nv_bfloat16 g_ql[Bdim*NN*NN];
__device__ __nv_bfloat16 g_dh[Bdim*NN*NN];   // [b][d][a]  (DA transposed)
__device__ __nv_bfloat16 g_dl[Bdim*NN*NN];
__device__ __nv_bfloat16 g_wh[Kdim*NN*NN];   // [k][d][e]
__device__ __nv_bfloat16 g_wl[Kdim*NN*NN];
__device__ float g_vq[Bdim*Kdim*NN];
__device__ float g_vd[Bdim*Kdim*NN];

// ---------------- helpers ----------------
__device__ __forceinline__ void cvt2(float x, __nv_bfloat16& h, __nv_bfloat16& l) {
    h = __float2bfloat16(x);
    l = __float2bfloat16(x - __bfloat162float(h));
}
__device__ __forceinline__ uint32_t pack2(__nv_bfloat16 a, __nv_bfloat16 b) {
    __nv_bfloat162 v(a, b);
    return *(uint32_t*)&v;
}
__device__ __forceinline__ float sigf(float x) { return 1.0f / (1.0f + __expf(-x)); }

// ---------------- prep kernels ----------------
// fused Q+W convert: blocks [0,4096) -> Q, [4096,5120) -> W
__global__ void cvt_qw_kernel(const float4* __restrict__ q4, const float4* __restrict__ w4) {
    if (blockIdx.x < 4096) {
        int i = blockIdx.x * 256 + threadIdx.x;
        float4 v = q4[i];
        __nv_bfloat16 h0,h1,h2,h3,l0,l1,l2,l3;
        cvt2(v.x,h0,l0); cvt2(v.y,h1,l1); cvt2(v.z,h2,l2); cvt2(v.w,h3,l3);
        ((uint2*)g_qh)[i] = make_uint2(pack2(h0,h1), pack2(h2,h3));
        ((uint2*)g_ql)[i] = make_uint2(pack2(l0,l1), pack2(l2,l3));
    } else {
        int i = (blockIdx.x - 4096) * 256 + threadIdx.x;
        float4 v = w4[i];
        __nv_bfloat16 h0,h1,h2,h3,l0,l1,l2,l3;
        cvt2(v.x,h0,l0); cvt2(v.y,h1,l1); cvt2(v.z,h2,l2); cvt2(v.w,h3,l3);
        ((uint2*)g_wh)[i] = make_uint2(pack2(h0,h1), pack2(h2,h3));
        ((uint2*)g_wl)[i] = make_uint2(pack2(l0,l1), pack2(l2,l3));
    }
}
// DA: [b][a][d] fp32 -> [b][d][a] bf16 hi/lo
__global__ void cvt_daT_kernel(const float* __restrict__ da) {
    __shared__ float tile[32][33];
    int b = blockIdx.z, a0 = blockIdx.x * 32, d0 = blockIdx.y * 32;
    int tx = threadIdx.x, ty = threadIdx.y;   // 32 x 8
    const float* src = da + ((size_t)b * NN + a0) * NN + d0;
    #pragma unroll
    for (int i = 0; i < 4; i++)
        tile[ty + 8*i][tx] = src[(size_t)(ty + 8*i) * NN + tx];
    __syncthreads();
    #pragma unroll
    for (int i = 0; i < 4; i++) {
        int dl = ty + 8*i;
        float v = tile[tx][dl];
        __nv_bfloat16 h, l; cvt2(v, h, l);
        size_t o = ((size_t)b * NN + d0 + dl) * NN + a0 + tx;
        g_dh[o] = h; g_dl[o] = l;
    }
}
// vqvd: grid 128 = b(64) x which(2), block 512 = row(256) x d-half(2); SMEM reduce
__global__ void vqvd_kernel(const float* __restrict__ q_em, const float* __restrict__ da_em,
                            const float* __restrict__ V) {
    __shared__ float Vs[16 * NN];    // 16KB; reused as reduction buffer after loop
    int b = blockIdx.x >> 1, which = blockIdx.x & 1;
    int t = threadIdx.x;             // 512 threads
    #pragma unroll
    for (int i = 0; i < 8; i++) {
        int idx = i * 512 + t, k = idx >> 8, d = idx & 255;
        Vs[idx] = V[k * 512 + which * 256 + d];
    }
    __syncthreads();
    int row = t & 255, half = t >> 8;
    const float* src = (which ? da_em : q_em) + (size_t)(b * NN + row) * NN;
    const float4* r4  = (const float4*)src + half * 32;
    const float4* Vs4 = (const float4*)Vs + half * 32;
    float acc[16];
    #pragma unroll
    for (int k = 0; k < 16; k++) acc[k] = 0.f;
    for (int d4 = 0; d4 < 32; d4++) {
        float4 x = r4[d4];
        #pragma unroll
        for (int k = 0; k < 16; k++) {
            float4 v = Vs4[k * 64 + d4];
            acc[k] += x.x*v.x + x.y*v.y + x.z*v.z + x.w*v.w;
        }
    }
    __syncthreads();                 // Vs loop reads done; safe to overwrite as red buffer
    if (half) {
        #pragma unroll
        for (int k = 0; k < 16; k++) Vs[k * 256 + row] = acc[k];
    }
    __syncthreads();
    if (!half) {
        float* dst = (which ? g_vd : g_vq);
        #pragma unroll
        for (int k = 0; k < 16; k++)
            dst[(b * 16 + k) * NN + row] = acc[k] + Vs[k * 256 + row];
    }
}

// ---------------- mma/ldsm wrappers ----------------
__device__ __forceinline__ void ldsm_x4(unsigned* r, uint32_t addr) {
    asm volatile("ldmatrix.sync.aligned.m8n8.x4.shared.b16 {%0,%1,%2,%3}, [%4];"
                 : "=r"(r[0]), "=r"(r[1]), "=r"(r[2]), "=r"(r[3]) : "r"(addr));
}
__device__ __forceinline__ void ldsm_x4t(unsigned* r, uint32_t addr) {
    asm volatile("ldmatrix.sync.aligned.m8n8.x4.trans.shared.b16 {%0,%1,%2,%3}, [%4];"
                 : "=r"(r[0]), "=r"(r[1]), "=r"(r[2]), "=r"(r[3]) : "r"(addr));
}
__device__ __forceinline__ void mma_bf16(float* c, const unsigned* a, unsigned b0, unsigned b1) {
    asm volatile("mma.sync.aligned.m16n8k16.row.col.f32.bf16.bf16.f32 "
                 "{%0,%1,%2,%3}, {%4,%5,%6,%7}, {%8,%9}, {%0,%1,%2,%3};"
                 : "+f"(c[0]), "+f"(c[1]), "+f"(c[2]), "+f"(c[3])
                 : "r"(a[0]), "r"(a[1]), "r"(a[2]), "r"(a[3]), "r"(b0), "r"(b1));
}
__device__ __forceinline__ void cpa16(uint32_t dst, const void* src) {
    asm volatile("cp.async.cg.shared.global [%0], [%1], 16;" :: "r"(dst), "l"(src) : "memory");
}
#define CP_COMMIT() asm volatile("cp.async.commit_group;" ::: "memory")
#define CP_WAIT(n)  asm volatile("cp.async.wait_group %0;" :: "n"(n) : "memory")

// ---------------- SMEM layout (bytes) ----------------
#define TS_H 0
#define TS_L 32768
#define S1_OFF 65536
#define S1_STRIDE 23552
#define QS_H 0
#define QS_L 3072
#define WS_H 6144
#define WS_L 14592
#define S2_OFF 65536               // alias of S1 region
#define S2_STRIDE 17408
#define DA_H 0
#define DA_L 8448
#define VQ_OFF (S1_OFF + 2*S1_STRIDE)   // 112640
#define VD_OFF (VQ_OFF + 256)
#define SMEM_TOTAL (VD_OFF + 1024)      // 113920

#define QP 24    // Q slab pitch (halves)
#define WP 264   // W / DA slab pitch (halves)

// Ts swizzled address: row r (0..63), 16B-unit u (0..31)
__device__ __forceinline__ uint32_t ts_addr(uint32_t base, int r, int u) {
    return base + (uint32_t)(r * 512) + (uint32_t)(((u ^ (r & 7)) << 4));
}

// ---------------- cp.async slab issuers ----------------
__device__ __forceinline__ void s1_issue(uint32_t buf,
    const __nv_bfloat16* qh, const __nv_bfloat16* ql,
    const __nv_bfloat16* wh, const __nv_bfloat16* wl, int d0, int t)
{
    {   // Q slab: 64 rows x 16 halves, hi+lo -> 256 tasks
        int arr = t >> 7, idx = t & 127, row = idx >> 1, ch = idx & 1;
        uint32_t dst = buf + (arr ? QS_L : QS_H) + (uint32_t)(row * QP + ch * 8) * 2;
        const __nv_bfloat16* src = (arr ? ql : qh) + (size_t)row * NN + d0 + ch * 8;
        cpa16(dst, src);
    }
    // W slab: 16 rows x 256 halves, hi+lo -> 1024 tasks
    #pragma unroll
    for (int i = 0; i < 4; i++) {
        int task = i * 256 + t;
        int arr = task >> 9, idx = task & 511, row = idx >> 5, ch = idx & 31;
        uint32_t dst = buf + (arr ? WS_L : WS_H) + (uint32_t)(row * WP + ch * 8) * 2;
        const __nv_bfloat16* src = (arr ? wl : wh) + (size_t)(d0 + row) * NN + ch * 8;
        cpa16(dst, src);
    }
    CP_COMMIT();
}
__device__ __forceinline__ void s2_issue(uint32_t buf,
    const __nv_bfloat16* dth, const __nv_bfloat16* dtl, int e0, int t)
{
    // DA^T slab: 16 rows (d) x 256 halves (a), hi+lo -> 1024 tasks
    #pragma unroll
    for (int i = 0; i < 4; i++) {
        int task = i * 256 + t;
        int arr = task >> 9, idx = task & 511, row = idx >> 5, ch = idx & 31;
        uint32_t dst = buf + (arr ? DA_L : DA_H) + (uint32_t)(row * WP + ch * 8) * 2;
        const __nv_bfloat16* src = (arr ? dtl : dth) + (size_t)(e0 + row) * NN + ch * 8;
        cpa16(dst, src);
    }
    CP_COMMIT();
}

// ---------------- main kernel (R10 exact — proven best) ----------------
__global__ void __launch_bounds__(256, 2)
ntn_mma_kernel(const float* __restrict__ bias, float* __restrict__ out)
{
    extern __shared__ char sm[];
    const uint32_t smb = (uint32_t)__cvta_generic_to_shared(sm);
    float* vq = (float*)(sm + VQ_OFF);
    float* vd = (float*)(sm + VD_OFF);

    const int t  = threadIdx.x;
    const int bx = blockIdx.x;
    const int qt = bx & 3;
    const int k  = (bx >> 2) & 15;
    const int b  = bx >> 6;
    const int q0 = qt * QT;
    const int bk = b * 16 + k;

    const int warp = t >> 5;
    const int lane = t & 31;
    const int wq   = warp >> 2;   // 0..1: 32 q-rows each
    const int we   = warp & 3;    // 0..3: 64 cols each
    const int grp  = lane >> 2;
    const int tig  = lane & 3;

    if (t < QT) vq[t] = g_vq[bk * NN + q0 + t];
    vd[t] = g_vd[bk * NN + t];

    const __nv_bfloat16* qh_p = g_qh + ((size_t)b * NN + q0) * NN;
    const __nv_bfloat16* ql_p = g_ql + ((size_t)b * NN + q0) * NN;
    const __nv_bfloat16* wh_p = g_wh + (size_t)k * NN * NN;
    const __nv_bfloat16* wl_p = g_wl + (size_t)k * NN * NN;
    const __nv_bfloat16* dh_p = g_dh + (size_t)b * NN * NN;
    const __nv_bfloat16* dl_p = g_dl + (size_t)b * NN * NN;

    float acc[2][8][4];
    #pragma unroll
    for (int m = 0; m < 2; m++)
        #pragma unroll
        for (int j = 0; j < 8; j++)
            #pragma unroll
            for (int c = 0; c < 4; c++) acc[m][j][c] = 0.f;

    const int a_row  = wq * 32 + (lane & 15);
    const int a_cu   = lane >> 4;
    const int bw_row = lane & 15;

    // =============== Stage 1: T[64][256] = Q @ W_k ===============
    s1_issue(smb + S1_OFF, qh_p, ql_p, wh_p, wl_p, 0, t);

    #pragma unroll 1
    for (int it = 0; it < 16; it++) {
        CP_WAIT(0);
        __syncthreads();
        if (it + 1 < 16)
            s1_issue(smb + S1_OFF + ((it + 1) & 1) * S1_STRIDE,
                     qh_p, ql_p, wh_p, wl_p, (it + 1) * 16, t);
        uint32_t cur = smb + S1_OFF + (it & 1) * S1_STRIDE;

        unsigned ah[2][4], al[2][4];
        uint32_t qa = cur + QS_H + (uint32_t)(a_row * QP + a_cu * 8) * 2;
        ldsm_x4(ah[0], qa);
        ldsm_x4(ah[1], qa + 16 * QP * 2);
        qa = cur + QS_L + (uint32_t)(a_row * QP + a_cu * 8) * 2;
        ldsm_x4(al[0], qa);
        ldsm_x4(al[1], qa + 16 * QP * 2);

        #pragma unroll
        for (int n2 = 0; n2 < 4; n2++) {
            uint32_t eoff = (uint32_t)(bw_row * WP + we * 64 + n2 * 16 + a_cu * 8) * 2;
            unsigned bh[4], bl[4];
            ldsm_x4t(bh, cur + WS_H + eoff);
            ldsm_x4t(bl, cur + WS_L + eoff);
            #pragma unroll
            for (int m = 0; m < 2; m++) {
                float* c0 = acc[m][2 * n2];
                float* c1 = acc[m][2 * n2 + 1];
                mma_bf16(c0, ah[m], bh[0], bh[1]);
                mma_bf16(c0, ah[m], bl[0], bl[1]);
                mma_bf16(c0, al[m], bh[0], bh[1]);
                mma_bf16(c1, ah[m], bh[2], bh[3]);
                mma_bf16(c1, ah[m], bl[2], bl[3]);
                mma_bf16(c1, al[m], bh[2], bh[3]);
            }
        }
    }

    s2_issue(smb + S2_OFF, dh_p, dl_p, 0, t);

    // -------- write T to swizzled SMEM as bf16 hi/lo --------
    #pragma unroll
    for (int m = 0; m < 2; m++) {
        int r0 = wq * 32 + m * 16 + grp;
        #pragma unroll
        for (int j = 0; j < 8; j++) {
            int u = we * 8 + j;
            __nv_bfloat16 h0, l0, h1, l1, h2, l2, h3, l3;
            cvt2(acc[m][j][0], h0, l0); cvt2(acc[m][j][1], h1, l1);
            cvt2(acc[m][j][2], h2, l2); cvt2(acc[m][j][3], h3, l3);
            uint32_t a0 = ts_addr(smb + TS_H, r0, u) + tig * 4;
            uint32_t a1 = ts_addr(smb + TS_H, r0 + 8, u) + tig * 4;
            uint32_t b0 = ts_addr(smb + TS_L, r0, u) + tig * 4;
            uint32_t b1 = ts_addr(smb + TS_L, r0 + 8, u) + tig * 4;
            uint32_t v;
            v = pack2(h0, h1); asm volatile("st.shared.b32 [%0], %1;" :: "r"(a0), "r"(v) : "memory");
            v = pack2(h2, h3); asm volatile("st.shared.b32 [%0], %1;" :: "r"(a1), "r"(v) : "memory");
            v = pack2(l0, l1); asm volatile("st.shared.b32 [%0], %1;" :: "r"(b0), "r"(v) : "memory");
            v = pack2(l2, l3); asm volatile("st.shared.b32 [%0], %1;" :: "r"(b1), "r"(v) : "memory");
        }
    }
    __syncthreads();

    // =============== Stage 2: OUT = T @ DA^T ===============
    #pragma unroll
    for (int m = 0; m < 2; m++)
        #pragma unroll
        for (int j = 0; j < 8; j++)
            #pragma unroll
            for (int c = 0; c < 4; c++) acc[m][j][c] = 0.f;

    #pragma unroll 1
    for (int it = 0; it < 16; it++) {
        unsigned ah[2][4], al[2][4];
        int u = it * 2 + a_cu;
        ldsm_x4(ah[0], ts_addr(smb + TS_H, a_row, u));
        ldsm_x4(ah[1], ts_addr(smb + TS_H, a_row + 16, u));
        ldsm_x4(al[0], ts_addr(smb + TS_L, a_row, u));
        ldsm_x4(al[1], ts_addr(smb + TS_L, a_row + 16, u));

        CP_WAIT(0);
        __syncthreads();
        if (it + 1 < 16)
            s2_issue(smb + S2_OFF + ((it + 1) & 1) * S2_STRIDE, dh_p, dl_p, (it + 1) * 16, t);
        uint32_t cur = smb + S2_OFF + (it & 1) * S2_STRIDE;

        #pragma unroll
        for (int n2 = 0; n2 < 4; n2++) {
            uint32_t aoff = (uint32_t)(bw_row * WP + we * 64 + n2 * 16 + a_cu * 8) * 2;
            unsigned bh[4], bl[4];
            ldsm_x4t(bh, cur + DA_H + aoff);
            ldsm_x4t(bl, cur + DA_L + aoff);
            #pragma unroll
            for (int m = 0; m < 2; m++) {
                float* c0 = acc[m][2 * n2];
                float* c1 = acc[m][2 * n2 + 1];
                mma_bf16(c0, ah[m], bh[0], bh[1]);
                mma_bf16(c0, ah[m], bl[0], bl[1]);
                mma_bf16(c0, al[m], bh[0], bh[1]);
                mma_bf16(c1, ah[m], bh[2], bh[3]);
                mma_bf16(c1, ah[m], bl[2], bl[3]);
                mma_bf16(c1, al[m], bh[2], bh[3]);
            }
        }
    }

    // =============== Epilogue: + vq + vd + bias, sigmoid ===============
    const float bkf = bias[k];
    float* ob = out + (((size_t)b * Kdim + k) * NN + q0) * (size_t)NN;
    #pragma unroll
    for (int m = 0; m < 2; m++) {
        int r0 = wq * 32 + m * 16 + grp;
        float vq0 = vq[r0], vq1 = vq[r0 + 8];
        #pragma unroll
        for (int j = 0; j < 8; j++) {
            int col = we * 64 + j * 8 + tig * 2;
            float vd0 = vd[col], vd1 = vd[col + 1];
            float2 o0, o1;
            o0.x = sigf(acc[m][j][0] + vq0 + vd0 + bkf);
            o0.y = sigf(acc[m][j][1] + vq0 + vd1 + bkf);
            o1.x = sigf(acc[m][j][2] + vq1 + vd0 + bkf);
            o1.y = sigf(acc[m][j][3] + vq1 + vd1 + bkf);
            *(float2*)&ob[(size_t)r0 * NN + col]       = o0;
            *(float2*)&ob[(size_t)(r0 + 8) * NN + col] = o1;
        }
    }
}

extern "C" void kernel_launch(void* const* d_in, const int* in_sizes, int n_in,
                              void* d_out, int out_size)
{
    (void)in_sizes; (void)n_in; (void)out_size;
    const float* q_em  = (const float*)d_in[0];
    const float* da_em = (const float*)d_in[1];
    const float* w     = (const float*)d_in[2];
    const float* V     = (const float*)d_in[3];
    const float* bias  = (const float*)d_in[4];
    float* out = (float*)d_out;

    cvt_qw_kernel<<<5120, 256>>>((const float4*)q_em, (const float4*)w);
    cvt_daT_kernel<<<dim3(8, 8, 64), dim3(32, 8)>>>(da_em);
    vqvd_kernel<<<128, 512>>>(q_em, da_em, V);

    cudaFuncSetAttribute(ntn_mma_kernel, cudaFuncAttributeMaxDynamicSharedMemorySize, SMEM_TOTAL);
    ntn_mma_kernel<<<4096, 256, SMEM_TOTAL>>>(bias, out);
}

// round 13
// speedup vs baseline: 1.3020x; 1.0069x over previous
#include <cuda_runtime.h>
#include <cuda_bf16.h>
#include <cstdint>

#define Bdim 64
#define Kdim 16
#define NN   256
#define QT   64

// ---------------- pre-converted operand scratch (device globals) ----------------
__device__ __nv_bfloat16 g_qh[Bdim*NN*NN];   // [b][q][d] hi
__device__ __nv_bfloat16 g_ql[Bdim*NN*NN];
__device__ __nv_bfloat16 g_dh[Bdim*NN*NN];   // [b][d][a]  (DA transposed)
__device__ __nv_bfloat16 g_dl[Bdim*NN*NN];
__device__ __nv_bfloat16 g_wh[Kdim*NN*NN];   // [k][d][e]
__device__ __nv_bfloat16 g_wl[Kdim*NN*NN];
__device__ float g_vq[Bdim*Kdim*NN];
__device__ float g_vd[Bdim*Kdim*NN];

// ---------------- helpers ----------------
__device__ __forceinline__ void cvt2(float x, __nv_bfloat16& h, __nv_bfloat16& l) {
    h = __float2bfloat16(x);
    l = __float2bfloat16(x - __bfloat162float(h));
}
__device__ __forceinline__ uint32_t pack2(__nv_bfloat16 a, __nv_bfloat16 b) {
    __nv_bfloat162 v(a, b);
    return *(uint32_t*)&v;
}
__device__ __forceinline__ float sigf(float x) { return 1.0f / (1.0f + __expf(-x)); }

// ---------------- prep kernels ----------------
// fused Q+W convert: blocks [0,4096) -> Q, [4096,5120) -> W
__global__ void cvt_qw_kernel(const float4* __restrict__ q4, const float4* __restrict__ w4) {
    if (blockIdx.x < 4096) {
        int i = blockIdx.x * 256 + threadIdx.x;
        float4 v = q4[i];
        __nv_bfloat16 h0,h1,h2,h3,l0,l1,l2,l3;
        cvt2(v.x,h0,l0); cvt2(v.y,h1,l1); cvt2(v.z,h2,l2); cvt2(v.w,h3,l3);
        ((uint2*)g_qh)[i] = make_uint2(pack2(h0,h1), pack2(h2,h3));
        ((uint2*)g_ql)[i] = make_uint2(pack2(l0,l1), pack2(l2,l3));
    } else {
        int i = (blockIdx.x - 4096) * 256 + threadIdx.x;
        float4 v = w4[i];
        __nv_bfloat16 h0,h1,h2,h3,l0,l1,l2,l3;
        cvt2(v.x,h0,l0); cvt2(v.y,h1,l1); cvt2(v.z,h2,l2); cvt2(v.w,h3,l3);
        ((uint2*)g_wh)[i] = make_uint2(pack2(h0,h1), pack2(h2,h3));
        ((uint2*)g_wl)[i] = make_uint2(pack2(l0,l1), pack2(l2,l3));
    }
}
// DA: [b][a][d] fp32 -> [b][d][a] bf16 hi/lo
__global__ void cvt_daT_kernel(const float* __restrict__ da) {
    __shared__ float tile[32][33];
    int b = blockIdx.z, a0 = blockIdx.x * 32, d0 = blockIdx.y * 32;
    int tx = threadIdx.x, ty = threadIdx.y;   // 32 x 8
    const float* src = da + ((size_t)b * NN + a0) * NN + d0;
    #pragma unroll
    for (int i = 0; i < 4; i++)
        tile[ty + 8*i][tx] = src[(size_t)(ty + 8*i) * NN + tx];
    __syncthreads();
    #pragma unroll
    for (int i = 0; i < 4; i++) {
        int dl = ty + 8*i;
        float v = tile[tx][dl];
        __nv_bfloat16 h, l; cvt2(v, h, l);
        size_t o = ((size_t)b * NN + d0 + dl) * NN + a0 + tx;
        g_dh[o] = h; g_dl[o] = l;
    }
}
// vqvd: grid 128 = b(64) x which(2), block 512 = row(256) x d-half(2); SMEM reduce
__global__ void vqvd_kernel(const float* __restrict__ q_em, const float* __restrict__ da_em,
                            const float* __restrict__ V) {
    __shared__ float Vs[16 * NN];
    int b = blockIdx.x >> 1, which = blockIdx.x & 1;
    int t = threadIdx.x;
    #pragma unroll
    for (int i = 0; i < 8; i++) {
        int idx = i * 512 + t, k = idx >> 8, d = idx & 255;
        Vs[idx] = V[k * 512 + which * 256 + d];
    }
    __syncthreads();
    int row = t & 255, half = t >> 8;
    const float* src = (which ? da_em : q_em) + (size_t)(b * NN + row) * NN;
    const float4* r4  = (const float4*)src + half * 32;
    const float4* Vs4 = (const float4*)Vs + half * 32;
    float acc[16];
    #pragma unroll
    for (int k = 0; k < 16; k++) acc[k] = 0.f;
    for (int d4 = 0; d4 < 32; d4++) {
        float4 x = r4[d4];
        #pragma unroll
        for (int k = 0; k < 16; k++) {
            float4 v = Vs4[k * 64 + d4];
            acc[k] += x.x*v.x + x.y*v.y + x.z*v.z + x.w*v.w;
        }
    }
    __syncthreads();
    if (half) {
        #pragma unroll
        for (int k = 0; k < 16; k++) Vs[k * 256 + row] = acc[k];
    }
    __syncthreads();
    if (!half) {
        float* dst = (which ? g_vd : g_vq);
        #pragma unroll
        for (int k = 0; k < 16; k++)
            dst[(b * 16 + k) * NN + row] = acc[k] + Vs[k * 256 + row];
    }
}

// ---------------- mma/ldsm wrappers ----------------
__device__ __forceinline__ void ldsm_x4(unsigned* r, uint32_t addr) {
    asm volatile("ldmatrix.sync.aligned.m8n8.x4.shared.b16 {%0,%1,%2,%3}, [%4];"
                 : "=r"(r[0]), "=r"(r[1]), "=r"(r[2]), "=r"(r[3]) : "r"(addr));
}
__device__ __forceinline__ void ldsm_x4t(unsigned* r, uint32_t addr) {
    asm volatile("ldmatrix.sync.aligned.m8n8.x4.trans.shared.b16 {%0,%1,%2,%3}, [%4];"
                 : "=r"(r[0]), "=r"(r[1]), "=r"(r[2]), "=r"(r[3]) : "r"(addr));
}
__device__ __forceinline__ void mma_bf16(float* c, const unsigned* a, unsigned b0, unsigned b1) {
    asm volatile("mma.sync.aligned.m16n8k16.row.col.f32.bf16.bf16.f32 "
                 "{%0,%1,%2,%3}, {%4,%5,%6,%7}, {%8,%9}, {%0,%1,%2,%3};"
                 : "+f"(c[0]), "+f"(c[1]), "+f"(c[2]), "+f"(c[3])
                 : "r"(a[0]), "r"(a[1]), "r"(a[2]), "r"(a[3]), "r"(b0), "r"(b1));
}
__device__ __forceinline__ void cpa16(uint32_t dst, const void* src) {
    asm volatile("cp.async.cg.shared.global [%0], [%1], 16;" :: "r"(dst), "l"(src) : "memory");
}
#define CP_COMMIT() asm volatile("cp.async.commit_group;" ::: "memory")
#define CP_WAIT(n)  asm volatile("cp.async.wait_group %0;" :: "n"(n) : "memory")

// ---------------- SMEM layout (bytes) ----------------
#define TS_H 0
#define TS_L 32768
#define S1_OFF 65536
#define S1_STRIDE 23552
#define QS_H 0
#define QS_L 3072
#define WS_H 6144
#define WS_L 14592
#define S2_OFF 65536               // alias of S1 region
#define S2_STRIDE 17408
#define DA_H 0
#define DA_L 8448
#define VQ_OFF (S1_OFF + 2*S1_STRIDE)   // 112640
#define VD_OFF (VQ_OFF + 256)
#define SMEM_TOTAL (VD_OFF + 1024)      // 113920

#define QP 24    // Q slab pitch (halves)
#define WP 264   // W / DA slab pitch (halves)

// Ts swizzled address: row r (0..63), 16B-unit u (0..31)
__device__ __forceinline__ uint32_t ts_addr(uint32_t base, int r, int u) {
    return base + (uint32_t)(r * 512) + (uint32_t)(((u ^ (r & 7)) << 4));
}

// ---------------- cp.async slab issuers ----------------
__device__ __forceinline__ void s1_issue(uint32_t buf,
    const __nv_bfloat16* qh, const __nv_bfloat16* ql,
    const __nv_bfloat16* wh, const __nv_bfloat16* wl, int d0, int t)
{
    {   // Q slab: 64 rows x 16 halves, hi+lo -> 256 tasks
        int arr = t >> 7, idx = t & 127, row = idx >> 1, ch = idx & 1;
        uint32_t dst = buf + (arr ? QS_L : QS_H) + (uint32_t)(row * QP + ch * 8) * 2;
        const __nv_bfloat16* src = (arr ? ql : qh) + (size_t)row * NN + d0 + ch * 8;
        cpa16(dst, src);
    }
    // W slab: 16 rows x 256 halves, hi+lo -> 1024 tasks
    #pragma unroll
    for (int i = 0; i < 4; i++) {
        int task = i * 256 + t;
        int arr = task >> 9, idx = task & 511, row = idx >> 5, ch = idx & 31;
        uint32_t dst = buf + (arr ? WS_L : WS_H) + (uint32_t)(row * WP + ch * 8) * 2;
        const __nv_bfloat16* src = (arr ? wl : wh) + (size_t)(d0 + row) * NN + ch * 8;
        cpa16(dst, src);
    }
    CP_COMMIT();
}
__device__ __forceinline__ void s2_issue(uint32_t buf,
    const __nv_bfloat16* dth, const __nv_bfloat16* dtl, int e0, int t)
{
    // DA^T slab: 16 rows (d) x 256 halves (a), hi+lo -> 1024 tasks
    #pragma unroll
    for (int i = 0; i < 4; i++) {
        int task = i * 256 + t;
        int arr = task >> 9, idx = task & 511, row = idx >> 5, ch = idx & 31;
        uint32_t dst = buf + (arr ? DA_L : DA_H) + (uint32_t)(row * WP + ch * 8) * 2;
        const __nv_bfloat16* src = (arr ? dtl : dth) + (size_t)(e0 + row) * NN + ch * 8;
        cpa16(dst, src);
    }
    CP_COMMIT();
}

// term-major 12-MMA block for one n2 group: dependent MMAs on the same acc are
// spaced 4 issues apart (beyond HMMA RAW latency), zero extra registers.
#define MMA_N2_BLOCK(accb, ah, al, bh, bl)                          \
    do {                                                            \
        mma_bf16((accb)[0], (ah)[0], (bh)[0], (bh)[1]);             \
        mma_bf16((accb)[1], (ah)[0], (bh)[2], (bh)[3]);             \
        mma_bf16((accb)[2], (ah)[1], (bh)[0], (bh)[1]);             \
        mma_bf16((accb)[3], (ah)[1], (bh)[2], (bh)[3]);             \
        mma_bf16((accb)[0], (ah)[0], (bl)[0], (bl)[1]);             \
        mma_bf16((accb)[1], (ah)[0], (bl)[2], (bl)[3]);             \
        mma_bf16((accb)[2], (ah)[1], (bl)[0], (bl)[1]);             \
        mma_bf16((accb)[3], (ah)[1], (bl)[2], (bl)[3]);             \
        mma_bf16((accb)[0], (al)[0], (bh)[0], (bh)[1]);             \
        mma_bf16((accb)[1], (al)[0], (bh)[2], (bh)[3]);             \
        mma_bf16((accb)[2], (al)[1], (bh)[0], (bh)[1]);             \
        mma_bf16((accb)[3], (al)[1], (bh)[2], (bh)[3]);             \
    } while (0)

// ---------------- main kernel ----------------
__global__ void __launch_bounds__(256, 2)
ntn_mma_kernel(const float* __restrict__ bias, float* __restrict__ out)
{
    extern __shared__ char sm[];
    const uint32_t smb = (uint32_t)__cvta_generic_to_shared(sm);
    float* vq = (float*)(sm + VQ_OFF);
    float* vd = (float*)(sm + VD_OFF);

    const int t  = threadIdx.x;
    const int bx = blockIdx.x;
    const int qt = bx & 3;
    const int k  = (bx >> 2) & 15;
    const int b  = bx >> 6;
    const int q0 = qt * QT;
    const int bk = b * 16 + k;

    const int warp = t >> 5;
    const int lane = t & 31;
    const int wq   = warp >> 2;   // 0..1: 32 q-rows each
    const int we   = warp & 3;    // 0..3: 64 cols each
    const int grp  = lane >> 2;
    const int tig  = lane & 3;

    if (t < QT) vq[t] = g_vq[bk * NN + q0 + t];
    vd[t] = g_vd[bk * NN + t];

    const __nv_bfloat16* qh_p = g_qh + ((size_t)b * NN + q0) * NN;
    const __nv_bfloat16* ql_p = g_ql + ((size_t)b * NN + q0) * NN;
    const __nv_bfloat16* wh_p = g_wh + (size_t)k * NN * NN;
    const __nv_bfloat16* wl_p = g_wl + (size_t)k * NN * NN;
    const __nv_bfloat16* dh_p = g_dh + (size_t)b * NN * NN;
    const __nv_bfloat16* dl_p = g_dl + (size_t)b * NN * NN;

    // acc4[n2][i]: i = {m0c0, m0c1, m1c0, m1c1} per n2 group
    float acc[4][4][4];
    #pragma unroll
    for (int n2 = 0; n2 < 4; n2++)
        #pragma unroll
        for (int i = 0; i < 4; i++)
            #pragma unroll
            for (int c = 0; c < 4; c++) acc[n2][i][c] = 0.f;

    const int a_row  = wq * 32 + (lane & 15);
    const int a_cu   = lane >> 4;
    const int bw_row = lane & 15;

    // =============== Stage 1: T[64][256] = Q @ W_k ===============
    s1_issue(smb + S1_OFF, qh_p, ql_p, wh_p, wl_p, 0, t);

    #pragma unroll 1
    for (int it = 0; it < 16; it++) {
        CP_WAIT(0);
        __syncthreads();
        if (it + 1 < 16)
            s1_issue(smb + S1_OFF + ((it + 1) & 1) * S1_STRIDE,
                     qh_p, ql_p, wh_p, wl_p, (it + 1) * 16, t);
        uint32_t cur = smb + S1_OFF + (it & 1) * S1_STRIDE;

        unsigned ah[2][4], al[2][4];
        uint32_t qa = cur + QS_H + (uint32_t)(a_row * QP + a_cu * 8) * 2;
        ldsm_x4(ah[0], qa);
        ldsm_x4(ah[1], qa + 16 * QP * 2);
        qa = cur + QS_L + (uint32_t)(a_row * QP + a_cu * 8) * 2;
        ldsm_x4(al[0], qa);
        ldsm_x4(al[1], qa + 16 * QP * 2);

        #pragma unroll
        for (int n2 = 0; n2 < 4; n2++) {
            uint32_t eoff = (uint32_t)(bw_row * WP + we * 64 + n2 * 16 + a_cu * 8) * 2;
            unsigned bh[4], bl[4];
            ldsm_x4t(bh, cur + WS_H + eoff);
            ldsm_x4t(bl, cur + WS_L + eoff);
            unsigned ap_h[2] = { 0, 0 }, ap_l[2] = { 0, 0 };
            (void)ap_h; (void)ap_l;
            float* accb[4] = { acc[n2][0], acc[n2][1], acc[n2][2], acc[n2][3] };
            unsigned ahx[2][4] = { { ah[0][0], ah[0][1], ah[0][2], ah[0][3] },
                                   { ah[1][0], ah[1][1], ah[1][2], ah[1][3] } };
            unsigned alx[2][4] = { { al[0][0], al[0][1], al[0][2], al[0][3] },
                                   { al[1][0], al[1][1], al[1][2], al[1][3] } };
            MMA_N2_BLOCK(accb, ahx, alx, bh, bl);
        }
    }

    s2_issue(smb + S2_OFF, dh_p, dl_p, 0, t);

    // -------- write T to swizzled SMEM as bf16 hi/lo --------
    // acc mapping: acc[n2][m*2+ci] holds (m16 tile m, n8 frag 2*n2+ci)
    #pragma unroll
    for (int n2 = 0; n2 < 4; n2++) {
        #pragma unroll
        for (int i = 0; i < 4; i++) {
            int m = i >> 1, ci = i & 1;
            int r0 = wq * 32 + m * 16 + grp;
            int j = 2 * n2 + ci;
            int u = we * 8 + j;
            __nv_bfloat16 h0, l0, h1, l1, h2, l2, h3, l3;
            cvt2(acc[n2][i][0], h0, l0); cvt2(acc[n2][i][1], h1, l1);
            cvt2(acc[n2][i][2], h2, l2); cvt2(acc[n2][i][3], h3, l3);
            uint32_t a0 = ts_addr(smb + TS_H, r0, u) + tig * 4;
            uint32_t a1 = ts_addr(smb + TS_H, r0 + 8, u) + tig * 4;
            uint32_t b0 = ts_addr(smb + TS_L, r0, u) + tig * 4;
            uint32_t b1 = ts_addr(smb + TS_L, r0 + 8, u) + tig * 4;
            uint32_t v;
            v = pack2(h0, h1); asm volatile("st.shared.b32 [%0], %1;" :: "r"(a0), "r"(v) : "memory");
            v = pack2(h2, h3); asm volatile("st.shared.b32 [%0], %1;" :: "r"(a1), "r"(v) : "memory");
            v = pack2(l0, l1); asm volatile("st.shared.b32 [%0], %1;" :: "r"(b0), "r"(v) : "memory");
            v = pack2(l2, l3); asm volatile("st.shared.b32 [%0], %1;" :: "r"(b1), "r"(v) : "memory");
        }
    }
    __syncthreads();   // Ts visible to all warps (enables hoisted A-ldsm below)

    // =============== Stage 2: OUT = T @ DA^T ===============
    #pragma unroll
    for (int n2 = 0; n2 < 4; n2++)
        #pragma unroll
        for (int i = 0; i < 4; i++)
            #pragma unroll
            for (int c = 0; c < 4; c++) acc[n2][i][c] = 0.f;

    #pragma unroll 1
    for (int it = 0; it < 16; it++) {
        // A frags from stable Ts region — hoisted above the wait to hide LDS latency
        unsigned ah[2][4], al[2][4];
        int u = it * 2 + a_cu;
        ldsm_x4(ah[0], ts_addr(smb + TS_H, a_row, u));
        ldsm_x4(ah[1], ts_addr(smb + TS_H, a_row + 16, u));
        ldsm_x4(al[0], ts_addr(smb + TS_L, a_row, u));
        ldsm_x4(al[1], ts_addr(smb + TS_L, a_row + 16, u));

        CP_WAIT(0);
        __syncthreads();
        if (it + 1 < 16)
            s2_issue(smb + S2_OFF + ((it + 1) & 1) * S2_STRIDE, dh_p, dl_p, (it + 1) * 16, t);
        uint32_t cur = smb + S2_OFF + (it & 1) * S2_STRIDE;

        #pragma unroll
        for (int n2 = 0; n2 < 4; n2++) {
            uint32_t aoff = (uint32_t)(bw_row * WP + we * 64 + n2 * 16 + a_cu * 8) * 2;
            unsigned bh[4], bl[4];
            ldsm_x4t(bh, cur + DA_H + aoff);
            ldsm_x4t(bl, cur + DA_L + aoff);
            float* accb[4] = { acc[n2][0], acc[n2][1], acc[n2][2], acc[n2][3] };
            unsigned ahx[2][4] = { { ah[0][0], ah[0][1], ah[0][2], ah[0][3] },
                                   { ah[1][0], ah[1][1], ah[1][2], ah[1][3] } };
            unsigned alx[2][4] = { { al[0][0], al[0][1], al[0][2], al[0][3] },
                                   { al[1][0], al[1][1], al[1][2], al[1][3] } };
            MMA_N2_BLOCK(accb, ahx, alx, bh, bl);
        }
    }

    // =============== Epilogue: + vq + vd + bias, sigmoid ===============
    const float bkf = bias[k];
    float* ob = out + (((size_t)b * Kdim + k) * NN + q0) * (size_t)NN;
    #pragma unroll
    for (int n2 = 0; n2 < 4; n2++) {
        #pragma unroll
        for (int i = 0; i < 4; i++) {
            int m = i >> 1, ci = i & 1;
            int r0 = wq * 32 + m * 16 + grp;
            int j = 2 * n2 + ci;
            int col = we * 64 + j * 8 + tig * 2;
            float vq0 = vq[r0], vq1 = vq[r0 + 8];
            float vd0 = vd[col], vd1 = vd[col + 1];
            float2 o0, o1;
            o0.x = sigf(acc[n2][i][0] + vq0 + vd0 + bkf);
            o0.y = sigf(acc[n2][i][1] + vq0 + vd1 + bkf);
            o1.x = sigf(acc[n2][i][2] + vq1 + vd0 + bkf);
            o1.y = sigf(acc[n2][i][3] + vq1 + vd1 + bkf);
            *(float2*)&ob[(size_t)r0 * NN + col]       = o0;
            *(float2*)&ob[(size_t)(r0 + 8) * NN + col] = o1;
        }
    }
}

extern "C" void kernel_launch(void* const* d_in, const int* in_sizes, int n_in,
                              void* d_out, int out_size)
{
    (void)in_sizes; (void)n_in; (void)out_size;
    const float* q_em  = (const float*)d_in[0];
    const float* da_em = (const float*)d_in[1];
    const float* w     = (const float*)d_in[2];
    const float* V     = (const float*)d_in[3];
    const float* bias  = (const float*)d_in[4];
    float* out = (float*)d_out;

    cvt_qw_kernel<<<5120, 256>>>((const float4*)q_em, (const float4*)w);
    cvt_daT_kernel<<<dim3(8, 8, 64), dim3(32, 8)>>>(da_em);
    vqvd_kernel<<<128, 512>>>(q_em, da_em, V);

    cudaFuncSetAttribute(ntn_mma_kernel, cudaFuncAttributeMaxDynamicSharedMemorySize, SMEM_TOTAL);
    ntn_mma_kernel<<<4096, 256, SMEM_TOTAL>>>(bias, out);
}

// round 14
// speedup vs baseline: 1.3163x; 1.0109x over previous
#include <cuda_runtime.h>
#include <cuda_bf16.h>
#include <cstdint>

#define Bdim 64
#define Kdim 16
#define NN   256
#define QT   64

// ---------------- pre-converted operand scratch (device globals) ----------------
__device__ __nv_bfloat16 g_qh[Bdim*NN*NN];   // [b][q][d] hi
__device__ __nv_bfloat16 g_ql[Bdim*NN*NN];
__device__ __nv_bfloat16 g_dh[Bdim*NN*NN];   // [b][d][a]  (DA transposed)
__device__ __nv_bfloat16 g_dl[Bdim*NN*NN];
__device__ __nv_bfloat16 g_wh[Kdim*NN*NN];   // [k][d][e]
__device__ __nv_bfloat16 g_wl[Kdim*NN*NN];
__device__ float g_vq[Bdim*Kdim*NN];
__device__ float g_vd[Bdim*Kdim*NN];

// ---------------- helpers ----------------
__device__ __forceinline__ void cvt2(float x, __nv_bfloat16& h, __nv_bfloat16& l) {
    h = __float2bfloat16(x);
    l = __float2bfloat16(x - __bfloat162float(h));
}
__device__ __forceinline__ uint32_t pack2(__nv_bfloat16 a, __nv_bfloat16 b) {
    __nv_bfloat162 v(a, b);
    return *(uint32_t*)&v;
}
__device__ __forceinline__ float sigf(float x) { return 1.0f / (1.0f + __expf(-x)); }

// ---------------- prep kernels ----------------
__global__ void cvt_qw_kernel(const float4* __restrict__ q4, const float4* __restrict__ w4) {
    if (blockIdx.x < 4096) {
        int i = blockIdx.x * 256 + threadIdx.x;
        float4 v = q4[i];
        __nv_bfloat16 h0,h1,h2,h3,l0,l1,l2,l3;
        cvt2(v.x,h0,l0); cvt2(v.y,h1,l1); cvt2(v.z,h2,l2); cvt2(v.w,h3,l3);
        ((uint2*)g_qh)[i] = make_uint2(pack2(h0,h1), pack2(h2,h3));
        ((uint2*)g_ql)[i] = make_uint2(pack2(l0,l1), pack2(l2,l3));
    } else {
        int i = (blockIdx.x - 4096) * 256 + threadIdx.x;
        float4 v = w4[i];
        __nv_bfloat16 h0,h1,h2,h3,l0,l1,l2,l3;
        cvt2(v.x,h0,l0); cvt2(v.y,h1,l1); cvt2(v.z,h2,l2); cvt2(v.w,h3,l3);
        ((uint2*)g_wh)[i] = make_uint2(pack2(h0,h1), pack2(h2,h3));
        ((uint2*)g_wl)[i] = make_uint2(pack2(l0,l1), pack2(l2,l3));
    }
}
// DA: [b][a][d] fp32 -> [b][d][a] bf16 hi/lo
__global__ void cvt_daT_kernel(const float* __restrict__ da) {
    __shared__ float tile[32][33];
    int b = blockIdx.z, a0 = blockIdx.x * 32, d0 = blockIdx.y * 32;
    int tx = threadIdx.x, ty = threadIdx.y;   // 32 x 8
    const float* src = da + ((size_t)b * NN + a0) * NN + d0;
    #pragma unroll
    for (int i = 0; i < 4; i++)
        tile[ty + 8*i][tx] = src[(size_t)(ty + 8*i) * NN + tx];
    __syncthreads();
    #pragma unroll
    for (int i = 0; i < 4; i++) {
        int dl = ty + 8*i;
        float v = tile[tx][dl];
        __nv_bfloat16 h, l; cvt2(v, h, l);
        size_t o = ((size_t)b * NN + d0 + dl) * NN + a0 + tx;
        g_dh[o] = h; g_dl[o] = l;
    }
}
// vqvd: grid 128 = b(64) x which(2), block 512 = row(256) x d-half(2); SMEM reduce
__global__ void vqvd_kernel(const float* __restrict__ q_em, const float* __restrict__ da_em,
                            const float* __restrict__ V) {
    __shared__ float Vs[16 * NN];
    int b = blockIdx.x >> 1, which = blockIdx.x & 1;
    int t = threadIdx.x;
    #pragma unroll
    for (int i = 0; i < 8; i++) {
        int idx = i * 512 + t, k = idx >> 8, d = idx & 255;
        Vs[idx] = V[k * 512 + which * 256 + d];
    }
    __syncthreads();
    int row = t & 255, half = t >> 8;
    const float* src = (which ? da_em : q_em) + (size_t)(b * NN + row) * NN;
    const float4* r4  = (const float4*)src + half * 32;
    const float4* Vs4 = (const float4*)Vs + half * 32;
    float acc[16];
    #pragma unroll
    for (int k = 0; k < 16; k++) acc[k] = 0.f;
    for (int d4 = 0; d4 < 32; d4++) {
        float4 x = r4[d4];
        #pragma unroll
        for (int k = 0; k < 16; k++) {
            float4 v = Vs4[k * 64 + d4];
            acc[k] += x.x*v.x + x.y*v.y + x.z*v.z + x.w*v.w;
        }
    }
    __syncthreads();
    if (half) {
        #pragma unroll
        for (int k = 0; k < 16; k++) Vs[k * 256 + row] = acc[k];
    }
    __syncthreads();
    if (!half) {
        float* dst = (which ? g_vd : g_vq);
        #pragma unroll
        for (int k = 0; k < 16; k++)
            dst[(b * 16 + k) * NN + row] = acc[k] + Vs[k * 256 + row];
    }
}

// ---------------- mma/ldsm wrappers ----------------
__device__ __forceinline__ void ldsm_x4(unsigned* r, uint32_t addr) {
    asm volatile("ldmatrix.sync.aligned.m8n8.x4.shared.b16 {%0,%1,%2,%3}, [%4];"
                 : "=r"(r[0]), "=r"(r[1]), "=r"(r[2]), "=r"(r[3]) : "r"(addr));
}
__device__ __forceinline__ void ldsm_x4t(unsigned* r, uint32_t addr) {
    asm volatile("ldmatrix.sync.aligned.m8n8.x4.trans.shared.b16 {%0,%1,%2,%3}, [%4];"
                 : "=r"(r[0]), "=r"(r[1]), "=r"(r[2]), "=r"(r[3]) : "r"(addr));
}
__device__ __forceinline__ void mma_bf16(float* c, const unsigned* a, unsigned b0, unsigned b1) {
    asm volatile("mma.sync.aligned.m16n8k16.row.col.f32.bf16.bf16.f32 "
                 "{%0,%1,%2,%3}, {%4,%5,%6,%7}, {%8,%9}, {%0,%1,%2,%3};"
                 : "+f"(c[0]), "+f"(c[1]), "+f"(c[2]), "+f"(c[3])
                 : "r"(a[0]), "r"(a[1]), "r"(a[2]), "r"(a[3]), "r"(b0), "r"(b1));
}
__device__ __forceinline__ void cpa16(uint32_t dst, const void* src) {
    asm volatile("cp.async.cg.shared.global [%0], [%1], 16;" :: "r"(dst), "l"(src) : "memory");
}
#define CP_COMMIT() asm volatile("cp.async.commit_group;" ::: "memory")
#define CP_WAIT(n)  asm volatile("cp.async.wait_group %0;" :: "n"(n) : "memory")

// ---------------- SMEM layout (bytes) ----------------
#define TS_H 0
#define TS_L 32768
#define S1_OFF 65536
#define S1_STRIDE 23552
#define QS_H 0
#define QS_L 3072
#define WS_H 6144
#define WS_L 14592
#define S2_OFF 65536               // alias of S1 region
#define S2_STRIDE 17408
#define DA_H 0
#define DA_L 8448
#define VQ_OFF (S1_OFF + 2*S1_STRIDE)   // 112640
#define VD_OFF (VQ_OFF + 256)
#define SMEM_TOTAL (VD_OFF + 1024)      // 113920

#define QP 24    // Q slab pitch (halves)
#define WP 264   // W / DA slab pitch (halves)

// Ts swizzled address: row r (0..63), 16B-unit u (0..31)
__device__ __forceinline__ uint32_t ts_addr(uint32_t base, int r, int u) {
    return base + (uint32_t)(r * 512) + (uint32_t)(((u ^ (r & 7)) << 4));
}

// ---------------- cp.async slab issuers ----------------
__device__ __forceinline__ void s1_issue(uint32_t buf,
    const __nv_bfloat16* qh, const __nv_bfloat16* ql,
    const __nv_bfloat16* wh, const __nv_bfloat16* wl, int d0, int t)
{
    {   // Q slab: 64 rows x 16 halves, hi+lo -> 256 tasks
        int arr = t >> 7, idx = t & 127, row = idx >> 1, ch = idx & 1;
        uint32_t dst = buf + (arr ? QS_L : QS_H) + (uint32_t)(row * QP + ch * 8) * 2;
        const __nv_bfloat16* src = (arr ? ql : qh) + (size_t)row * NN + d0 + ch * 8;
        cpa16(dst, src);
    }
    // W slab: 16 rows x 256 halves, hi+lo -> 1024 tasks
    #pragma unroll
    for (int i = 0; i < 4; i++) {
        int task = i * 256 + t;
        int arr = task >> 9, idx = task & 511, row = idx >> 5, ch = idx & 31;
        uint32_t dst = buf + (arr ? WS_L : WS_H) + (uint32_t)(row * WP + ch * 8) * 2;
        const __nv_bfloat16* src = (arr ? wl : wh) + (size_t)(d0 + row) * NN + ch * 8;
        cpa16(dst, src);
    }
    CP_COMMIT();
}
__device__ __forceinline__ void s2_issue(uint32_t buf,
    const __nv_bfloat16* dth, const __nv_bfloat16* dtl, int e0, int t)
{
    // DA^T slab: 16 rows (d) x 256 halves (a), hi+lo -> 1024 tasks
    #pragma unroll
    for (int i = 0; i < 4; i++) {
        int task = i * 256 + t;
        int arr = task >> 9, idx = task & 511, row = idx >> 5, ch = idx & 31;
        uint32_t dst = buf + (arr ? DA_L : DA_H) + (uint32_t)(row * WP + ch * 8) * 2;
        const __nv_bfloat16* src = (arr ? dtl : dth) + (size_t)(e0 + row) * NN + ch * 8;
        cpa16(dst, src);
    }
    CP_COMMIT();
}

// term-major 12-MMA block for one n2 group
#define MMA_N2_BLOCK(accb, ah, al, bh, bl)                          \
    do {                                                            \
        mma_bf16((accb)[0], (ah)[0], (bh)[0], (bh)[1]);             \
        mma_bf16((accb)[1], (ah)[0], (bh)[2], (bh)[3]);             \
        mma_bf16((accb)[2], (ah)[1], (bh)[0], (bh)[1]);             \
        mma_bf16((accb)[3], (ah)[1], (bh)[2], (bh)[3]);             \
        mma_bf16((accb)[0], (ah)[0], (bl)[0], (bl)[1]);             \
        mma_bf16((accb)[1], (ah)[0], (bl)[2], (bl)[3]);             \
        mma_bf16((accb)[2], (ah)[1], (bl)[0], (bl)[1]);             \
        mma_bf16((accb)[3], (ah)[1], (bl)[2], (bl)[3]);             \
        mma_bf16((accb)[0], (al)[0], (bh)[0], (bh)[1]);             \
        mma_bf16((accb)[1], (al)[0], (bh)[2], (bh)[3]);             \
        mma_bf16((accb)[2], (al)[1], (bh)[0], (bh)[1]);             \
        mma_bf16((accb)[3], (al)[1], (bh)[2], (bh)[3]);             \
    } while (0)

// ---------------- main kernel ----------------
__global__ void __launch_bounds__(256, 2)
ntn_mma_kernel(const float* __restrict__ bias, float* __restrict__ out)
{
    extern __shared__ char sm[];
    const uint32_t smb = (uint32_t)__cvta_generic_to_shared(sm);
    float* vq = (float*)(sm + VQ_OFF);
    float* vd = (float*)(sm + VD_OFF);

    const int t  = threadIdx.x;
    const int bx = blockIdx.x;
    const int qt = bx & 3;
    const int k  = (bx >> 2) & 15;
    const int b  = bx >> 6;
    const int q0 = qt * QT;
    const int bk = b * 16 + k;

    const int warp = t >> 5;
    const int lane = t & 31;
    const int wq   = warp >> 2;
    const int we   = warp & 3;
    const int grp  = lane >> 2;
    const int tig  = lane & 3;

    if (t < QT) vq[t] = g_vq[bk * NN + q0 + t];
    vd[t] = g_vd[bk * NN + t];

    const __nv_bfloat16* qh_p = g_qh + ((size_t)b * NN + q0) * NN;
    const __nv_bfloat16* ql_p = g_ql + ((size_t)b * NN + q0) * NN;
    const __nv_bfloat16* wh_p = g_wh + (size_t)k * NN * NN;
    const __nv_bfloat16* wl_p = g_wl + (size_t)k * NN * NN;
    const __nv_bfloat16* dh_p = g_dh + (size_t)b * NN * NN;
    const __nv_bfloat16* dl_p = g_dl + (size_t)b * NN * NN;

    // acc[n2][i]: i = {m0c0, m0c1, m1c0, m1c1}
    float acc[4][4][4];
    #pragma unroll
    for (int n2 = 0; n2 < 4; n2++)
        #pragma unroll
        for (int i = 0; i < 4; i++)
            #pragma unroll
            for (int c = 0; c < 4; c++) acc[n2][i][c] = 0.f;

    const int a_row  = wq * 32 + (lane & 15);
    const int a_cu   = lane >> 4;
    const int bw_row = lane & 15;
    // per-warp B base offset within slab (add n2*16*2 per group)
    const uint32_t b_off0 = (uint32_t)(bw_row * WP + we * 64 + a_cu * 8) * 2;

    // =============== Stage 1: T[64][256] = Q @ W_k ===============
    s1_issue(smb + S1_OFF, qh_p, ql_p, wh_p, wl_p, 0, t);

    #pragma unroll 1
    for (int it = 0; it < 16; it++) {
        CP_WAIT(0);
        __syncthreads();
        if (it + 1 < 16)
            s1_issue(smb + S1_OFF + ((it + 1) & 1) * S1_STRIDE,
                     qh_p, ql_p, wh_p, wl_p, (it + 1) * 16, t);
        uint32_t cur = smb + S1_OFF + (it & 1) * S1_STRIDE;

        unsigned ah[2][4], al[2][4];
        uint32_t qa = cur + QS_H + (uint32_t)(a_row * QP + a_cu * 8) * 2;
        ldsm_x4(ah[0], qa);
        ldsm_x4(ah[1], qa + 16 * QP * 2);
        qa = cur + QS_L + (uint32_t)(a_row * QP + a_cu * 8) * 2;
        ldsm_x4(al[0], qa);
        ldsm_x4(al[1], qa + 16 * QP * 2);

        // software-pipelined B fragments across n2 groups
        unsigned bh[2][4], bl[2][4];
        ldsm_x4t(bh[0], cur + WS_H + b_off0);
        ldsm_x4t(bl[0], cur + WS_L + b_off0);
        #pragma unroll
        for (int n2 = 0; n2 < 4; n2++) {
            int c = n2 & 1;
            if (n2 < 3) {
                uint32_t eoff = b_off0 + (uint32_t)((n2 + 1) * 16) * 2;
                ldsm_x4t(bh[c ^ 1], cur + WS_H + eoff);
                ldsm_x4t(bl[c ^ 1], cur + WS_L + eoff);
            }
            float* accb[4] = { acc[n2][0], acc[n2][1], acc[n2][2], acc[n2][3] };
            MMA_N2_BLOCK(accb, ah, al, bh[c], bl[c]);
        }
    }

    s2_issue(smb + S2_OFF, dh_p, dl_p, 0, t);

    // -------- write T to swizzled SMEM as bf16 hi/lo --------
    #pragma unroll
    for (int n2 = 0; n2 < 4; n2++) {
        #pragma unroll
        for (int i = 0; i < 4; i++) {
            int m = i >> 1, ci = i & 1;
            int r0 = wq * 32 + m * 16 + grp;
            int j = 2 * n2 + ci;
            int u = we * 8 + j;
            __nv_bfloat16 h0, l0, h1, l1, h2, l2, h3, l3;
            cvt2(acc[n2][i][0], h0, l0); cvt2(acc[n2][i][1], h1, l1);
            cvt2(acc[n2][i][2], h2, l2); cvt2(acc[n2][i][3], h3, l3);
            uint32_t a0 = ts_addr(smb + TS_H, r0, u) + tig * 4;
            uint32_t a1 = ts_addr(smb + TS_H, r0 + 8, u) + tig * 4;
            uint32_t b0 = ts_addr(smb + TS_L, r0, u) + tig * 4;
            uint32_t b1 = ts_addr(smb + TS_L, r0 + 8, u) + tig * 4;
            uint32_t v;
            v = pack2(h0, h1); asm volatile("st.shared.b32 [%0], %1;" :: "r"(a0), "r"(v) : "memory");
            v = pack2(h2, h3); asm volatile("st.shared.b32 [%0], %1;" :: "r"(a1), "r"(v) : "memory");
            v = pack2(l0, l1); asm volatile("st.shared.b32 [%0], %1;" :: "r"(b0), "r"(v) : "memory");
            v = pack2(l2, l3); asm volatile("st.shared.b32 [%0], %1;" :: "r"(b1), "r"(v) : "memory");
        }
    }
    __syncthreads();   // Ts visible to all warps

    // =============== Stage 2: OUT = T @ DA^T ===============
    #pragma unroll
    for (int n2 = 0; n2 < 4; n2++)
        #pragma unroll
        for (int i = 0; i < 4; i++)
            #pragma unroll
            for (int c = 0; c < 4; c++) acc[n2][i][c] = 0.f;

    #pragma unroll 1
    for (int it = 0; it < 16; it++) {
        // A frags from stable Ts region — hoisted above the wait
        unsigned ah[2][4], al[2][4];
        int u = it * 2 + a_cu;
        ldsm_x4(ah[0], ts_addr(smb + TS_H, a_row, u));
        ldsm_x4(ah[1], ts_addr(smb + TS_H, a_row + 16, u));
        ldsm_x4(al[0], ts_addr(smb + TS_L, a_row, u));
        ldsm_x4(al[1], ts_addr(smb + TS_L, a_row + 16, u));

        CP_WAIT(0);
        __syncthreads();
        if (it + 1 < 16)
            s2_issue(smb + S2_OFF + ((it + 1) & 1) * S2_STRIDE, dh_p, dl_p, (it + 1) * 16, t);
        uint32_t cur = smb + S2_OFF + (it & 1) * S2_STRIDE;

        // software-pipelined B fragments
        unsigned bh[2][4], bl[2][4];
        ldsm_x4t(bh[0], cur + DA_H + b_off0);
        ldsm_x4t(bl[0], cur + DA_L + b_off0);
        #pragma unroll
        for (int n2 = 0; n2 < 4; n2++) {
            int c = n2 & 1;
            if (n2 < 3) {
                uint32_t aoff = b_off0 + (uint32_t)((n2 + 1) * 16) * 2;
                ldsm_x4t(bh[c ^ 1], cur + DA_H + aoff);
                ldsm_x4t(bl[c ^ 1], cur + DA_L + aoff);
            }
            float* accb[4] = { acc[n2][0], acc[n2][1], acc[n2][2], acc[n2][3] };
            MMA_N2_BLOCK(accb, ah, al, bh[c], bl[c]);
        }
    }

    // =============== Epilogue: + vq + vd + bias, sigmoid ===============
    const float bkf = bias[k];
    float* ob = out + (((size_t)b * Kdim + k) * NN + q0) * (size_t)NN;
    #pragma unroll
    for (int n2 = 0; n2 < 4; n2++) {
        #pragma unroll
        for (int i = 0; i < 4; i++) {
            int m = i >> 1, ci = i & 1;
            int r0 = wq * 32 + m * 16 + grp;
            int j = 2 * n2 + ci;
            int col = we * 64 + j * 8 + tig * 2;
            float vq0 = vq[r0], vq1 = vq[r0 + 8];
            float vd0 = vd[col], vd1 = vd[col + 1];
            float2 o0, o1;
            o0.x = sigf(acc[n2][i][0] + vq0 + vd0 + bkf);
            o0.y = sigf(acc[n2][i][1] + vq0 + vd1 + bkf);
            o1.x = sigf(acc[n2][i][2] + vq1 + vd0 + bkf);
            o1.y = sigf(acc[n2][i][3] + vq1 + vd1 + bkf);
            *(float2*)&ob[(size_t)r0 * NN + col]       = o0;
            *(float2*)&ob[(size_t)(r0 + 8) * NN + col] = o1;
        }
    }
}

extern "C" void kernel_launch(void* const* d_in, const int* in_sizes, int n_in,
                              void* d_out, int out_size)
{
    (void)in_sizes; (void)n_in; (void)out_size;
    const float* q_em  = (const float*)d_in[0];
    const float* da_em = (const float*)d_in[1];
    const float* w     = (const float*)d_in[2];
    const float* V     = (const float*)d_in[3];
    const float* bias  = (const float*)d_in[4];
    float* out = (float*)d_out;

    cvt_qw_kernel<<<5120, 256>>>((const float4*)q_em, (const float4*)w);
    cvt_daT_kernel<<<dim3(8, 8, 64), dim3(32, 8)>>>(da_em);
    vqvd_kernel<<<128, 512>>>(q_em, da_em, V);

    cudaFuncSetAttribute(ntn_mma_kernel, cudaFuncAttributeMaxDynamicSharedMemorySize, SMEM_TOTAL);
    ntn_mma_kernel<<<4096, 256, SMEM_TOTAL>>>(bias, out);
}